// round 2
// baseline (speedup 1.0000x reference)
#include <cuda_runtime.h>
#include <cstddef>

// Problem constants
#define BSZ  256
#define TLEN 512
#define DIN  64

// ---------------------------------------------------------------------------
// Scratch (device globals — allocation-free per harness rules)
// ---------------------------------------------------------------------------
__device__ float g_xW[BSZ * TLEN * 1024];     // 512 MB: xW = x@W + b (largest layer)
__device__ float g_hseq[BSZ * TLEN * 256];    // 128 MB: h sequence of current layer
__device__ unsigned int g_bar_cnt;            // software grid barrier
__device__ unsigned int g_bar_gen;

// ---------------------------------------------------------------------------
// Software grid barrier for persistent kernels (grid <= #SMs, 1 CTA/SM).
// gen is monotonic across launches/replays; cnt self-resets -> graph-safe.
// Thread 0 arrives; ALL threads spin on the gen flip (with nanosleep backoff)
// so release visibility does not depend solely on __syncthreads ordering.
// ---------------------------------------------------------------------------
__device__ __forceinline__ void grid_barrier() {
    __syncthreads();
    unsigned int gen;
    if (threadIdx.x == 0) {
        __threadfence();  // make this CTA's h stores visible before arriving
        gen = *(volatile unsigned int*)&g_bar_gen;
        unsigned int arr = atomicAdd(&g_bar_cnt, 1u);
        if (arr == gridDim.x - 1u) {
            g_bar_cnt = 0u;
            __threadfence();
            atomicAdd(&g_bar_gen, 1u);  // release
        } else {
            int backoff = 32;
            while (*(volatile unsigned int*)&g_bar_gen == gen) {
                __nanosleep(backoff);
                if (backoff < 1024) backoff <<= 1;
            }
        }
        __threadfence();  // acquire
    }
    __syncthreads();
}

// ---------------------------------------------------------------------------
// Precompute GEMM: C[M,N] = A[M,K] @ W[K,N] + bias[N]
// BM=128, BN=128, BK=16, 256 threads, 8x8 micro-tile (FMA-issue-bound)
// ---------------------------------------------------------------------------
__global__ __launch_bounds__(256)
void gemm_bias(const float* __restrict__ A, const float* __restrict__ W,
               const float* __restrict__ bias, float* __restrict__ C,
               int M, int K, int N)
{
    __shared__ float As[16][128 + 4];  // transposed A tile: As[k][m]
    __shared__ float Ws[16][128 + 4];  // Ws[k][n]

    const int bm = blockIdx.y * 128;
    const int bn = blockIdx.x * 128;
    const int tid = threadIdx.x;
    const int tx = tid & 15;   // n dir
    const int ty = tid >> 4;   // m dir

    float acc[8][8];
#pragma unroll
    for (int i = 0; i < 8; i++)
#pragma unroll
        for (int j = 0; j < 8; j++) acc[i][j] = 0.f;

    for (int k0 = 0; k0 < K; k0 += 16) {
        // Load A tile (128 rows x 16 k) as 512 float4, transpose into As
#pragma unroll
        for (int l = 0; l < 2; l++) {
            int idx = tid + l * 256;          // 0..511
            int row = idx >> 2;
            int kq  = (idx & 3) * 4;
            float4 a = *(const float4*)&A[(size_t)(bm + row) * K + k0 + kq];
            As[kq + 0][row] = a.x;
            As[kq + 1][row] = a.y;
            As[kq + 2][row] = a.z;
            As[kq + 3][row] = a.w;
        }
        // Load W tile (16 k x 128 n)
#pragma unroll
        for (int l = 0; l < 2; l++) {
            int idx = tid + l * 256;
            int kk = idx >> 5;                // 32 float4 per row
            int nq = (idx & 31) * 4;
            float4 w = *(const float4*)&W[(size_t)(k0 + kk) * N + bn + nq];
            *(float4*)&Ws[kk][nq] = w;
        }
        __syncthreads();

#pragma unroll
        for (int k = 0; k < 16; k++) {
            float ar[8], wr[8];
            *(float4*)&ar[0] = *(const float4*)&As[k][ty * 8];
            *(float4*)&ar[4] = *(const float4*)&As[k][ty * 8 + 4];
            *(float4*)&wr[0] = *(const float4*)&Ws[k][tx * 8];
            *(float4*)&wr[4] = *(const float4*)&Ws[k][tx * 8 + 4];
#pragma unroll
            for (int i = 0; i < 8; i++)
#pragma unroll
                for (int j = 0; j < 8; j++)
                    acc[i][j] = fmaf(ar[i], wr[j], acc[i][j]);
        }
        __syncthreads();
    }

    // Epilogue: + bias
#pragma unroll
    for (int i = 0; i < 8; i++) {
        size_t row = (size_t)(bm + ty * 8 + i);
#pragma unroll
        for (int j = 0; j < 8; j += 4) {
            int col = bn + tx * 8 + j;
            float4 o;
            o.x = acc[i][j + 0] + bias[col + 0];
            o.y = acc[i][j + 1] + bias[col + 1];
            o.z = acc[i][j + 2] + bias[col + 2];
            o.w = acc[i][j + 3] + bias[col + 3];
            *(float4*)&C[row * N + col] = o;
        }
    }
}

// ---------------------------------------------------------------------------
// Persistent LSTM recurrence kernel.
//   Grid = (B/64) batch-blocks x (H/8) col-blocks, blockDim = 128.
//   Each thread owns 4 batch rows x 1 H-column -> 4 cells; c-state in regs.
//   U slice (4 gates x 8 cols x K) resident in shared for all T steps.
//   h exchanged via g_hseq with a grid barrier per step.
//   Keras gate order in z: [i | f | g | o], c = f*c + i*g, h = o*tanh(c).
// ---------------------------------------------------------------------------
__device__ __forceinline__ float sigmoidf_(float x) {
    return 1.f / (1.f + __expf(-x));
}

template<int H>
__global__ __launch_bounds__(128, 1)
void lstm_kernel(const float* __restrict__ xW, const float* __restrict__ U,
                 float* __restrict__ hseq)
{
    constexpr int K      = H;
    constexpr int KP     = K + 4;         // pad for bank-conflict-free float4
    constexpr int FOURH  = 4 * H;
    constexpr int NCB    = H / 8;         // column blocks

    __shared__ float Us[4 * 8 * KP];      // [gate][col][k]

    const int bx  = blockIdx.x;
    const int cb  = bx % NCB;
    const int bb  = bx / NCB;             // batch block (64 rows)
    const int tid = threadIdx.x;
    const int cc  = tid & 7;              // column within block
    const int bg  = tid >> 3;             // 0..15 -> 4 rows each
    const int c0  = cb * 8;
    const int b0  = bb * 64 + bg * 4;

    // Load persistent U slice: Us[(g*8+col)*KP + k] = U[k*4H + g*H + c0+col]
    for (int idx = tid; idx < 4 * 8 * K; idx += 128) {
        int col = idx & 7;
        int k   = (idx >> 3) % K;
        int g   = idx / (8 * K);
        Us[(g * 8 + col) * KP + k] = U[(size_t)k * FOURH + g * H + c0 + col];
    }
    __syncthreads();

    const float* UsI = &Us[(0 * 8 + cc) * KP];
    const float* UsF = &Us[(1 * 8 + cc) * KP];
    const float* UsG = &Us[(2 * 8 + cc) * KP];
    const float* UsO = &Us[(3 * 8 + cc) * KP];

    float cst[4] = {0.f, 0.f, 0.f, 0.f};

    for (int t = 0; t < TLEN; t++) {
        float acc[4][4];  // [gate][row]
        // init accumulators from precomputed xW (includes bias)
#pragma unroll
        for (int i = 0; i < 4; i++) {
            const float* xwrow =
                &xW[((size_t)(b0 + i) * TLEN + t) * FOURH + c0 + cc];
            acc[0][i] = xwrow[0 * H];
            acc[1][i] = xwrow[1 * H];
            acc[2][i] = xwrow[2 * H];
            acc[3][i] = xwrow[3 * H];
        }

        if (t > 0) {
            const float* hbase = &hseq[((size_t)b0 * TLEN + (t - 1)) * H];
#pragma unroll 2
            for (int k = 0; k < K; k += 4) {
                float4 ui = *(const float4*)(UsI + k);
                float4 uf = *(const float4*)(UsF + k);
                float4 ug = *(const float4*)(UsG + k);
                float4 uo = *(const float4*)(UsO + k);
#pragma unroll
                for (int i = 0; i < 4; i++) {
                    float4 hv = *(const float4*)(hbase + (size_t)i * TLEN * H + k);
                    acc[0][i] = fmaf(hv.x, ui.x, acc[0][i]);
                    acc[0][i] = fmaf(hv.y, ui.y, acc[0][i]);
                    acc[0][i] = fmaf(hv.z, ui.z, acc[0][i]);
                    acc[0][i] = fmaf(hv.w, ui.w, acc[0][i]);
                    acc[1][i] = fmaf(hv.x, uf.x, acc[1][i]);
                    acc[1][i] = fmaf(hv.y, uf.y, acc[1][i]);
                    acc[1][i] = fmaf(hv.z, uf.z, acc[1][i]);
                    acc[1][i] = fmaf(hv.w, uf.w, acc[1][i]);
                    acc[2][i] = fmaf(hv.x, ug.x, acc[2][i]);
                    acc[2][i] = fmaf(hv.y, ug.y, acc[2][i]);
                    acc[2][i] = fmaf(hv.z, ug.z, acc[2][i]);
                    acc[2][i] = fmaf(hv.w, ug.w, acc[2][i]);
                    acc[3][i] = fmaf(hv.x, uo.x, acc[3][i]);
                    acc[3][i] = fmaf(hv.y, uo.y, acc[3][i]);
                    acc[3][i] = fmaf(hv.z, uo.z, acc[3][i]);
                    acc[3][i] = fmaf(hv.w, uo.w, acc[3][i]);
                }
            }
        }

        // Gates + state update + h write
#pragma unroll
        for (int i = 0; i < 4; i++) {
            float ig = sigmoidf_(acc[0][i]);
            float fg = sigmoidf_(acc[1][i]);
            float gg = tanhf(acc[2][i]);
            float og = sigmoidf_(acc[3][i]);
            float cn = (t == 0) ? ig * gg : fmaf(fg, cst[i], ig * gg);
            cst[i] = cn;
            float hn = og * tanhf(cn);
            hseq[((size_t)(b0 + i) * TLEN + t) * H + c0 + cc] = hn;
        }

        grid_barrier();
    }
}

// ---------------------------------------------------------------------------
// Final dense: out[b,d] = hseq[b, T-1, :128] @ Wd[128,64] + bd[64]
// ---------------------------------------------------------------------------
__global__ void dense_kernel(const float* __restrict__ hseq,
                             const float* __restrict__ Wd,
                             const float* __restrict__ bd,
                             float* __restrict__ out)
{
    int b = blockIdx.x;    // 256
    int d = threadIdx.x;   // 64
    const float* h = &hseq[((size_t)b * TLEN + (TLEN - 1)) * 128];
    float acc = 0.f;
#pragma unroll 4
    for (int k = 0; k < 128; k++)
        acc = fmaf(h[k], Wd[k * 64 + d], acc);
    out[b * 64 + d] = acc + bd[d];
}

// ---------------------------------------------------------------------------
// Launch: 7 kernels, sequential on the capture stream.
//   xW0 -> LSTM0 -> xW1 -> LSTM1 -> xW2 -> LSTM2 -> dense
// ---------------------------------------------------------------------------
extern "C" void kernel_launch(void* const* d_in, const int* in_sizes, int n_in,
                              void* d_out, int out_size)
{
    (void)in_sizes; (void)n_in; (void)out_size;
    const float* x  = (const float*)d_in[0];
    const float* W0 = (const float*)d_in[1];
    const float* U0 = (const float*)d_in[2];
    const float* b0 = (const float*)d_in[3];
    const float* W1 = (const float*)d_in[4];
    const float* U1 = (const float*)d_in[5];
    const float* b1 = (const float*)d_in[6];
    const float* W2 = (const float*)d_in[7];
    const float* U2 = (const float*)d_in[8];
    const float* b2 = (const float*)d_in[9];
    const float* Wd = (const float*)d_in[10];
    const float* bd = (const float*)d_in[11];
    float* out = (float*)d_out;

    void* p;
    cudaGetSymbolAddress(&p, g_xW);   float* xw = (float*)p;
    cudaGetSymbolAddress(&p, g_hseq); float* hs = (float*)p;

    const int M = BSZ * TLEN;  // 131072

    // Layer 0: xW = x @ W0 + b0 (K=64, N=1024), then recurrence H=256
    gemm_bias<<<dim3(8, M / 128), 256>>>(x, W0, b0, xw, M, 64, 1024);
    lstm_kernel<256><<<(BSZ / 64) * (256 / 8), 128>>>(xw, U0, hs);   // 128 CTAs

    // Layer 1: K=256, N=1024
    gemm_bias<<<dim3(8, M / 128), 256>>>(hs, W1, b1, xw, M, 256, 1024);
    lstm_kernel<256><<<(BSZ / 64) * (256 / 8), 128>>>(xw, U1, hs);   // 128 CTAs

    // Layer 2: K=256, N=512, H=128
    gemm_bias<<<dim3(4, M / 128), 256>>>(hs, W2, b2, xw, M, 256, 512);
    lstm_kernel<128><<<(BSZ / 64) * (128 / 8), 128>>>(xw, U2, hs);   // 64 CTAs

    // Dense head
    dense_kernel<<<BSZ, 64>>>(hs, Wd, bd, out);
}

// round 5
// speedup vs baseline: 1.2471x; 1.2471x over previous
#include <cuda_runtime.h>
#include <cuda_bf16.h>
#include <cstdint>
#include <cstddef>

#define BSZ  256
#define TLEN 512
#define DIN  64
#define MTOT (BSZ * TLEN)

// ---------------------------------------------------------------------------
// Device-global scratch (allocation-free per harness rules)
// ---------------------------------------------------------------------------
__device__ float g_xW[MTOT * 1024];            // xW = x@W + b (largest layer)
__device__ float g_hseq[MTOT * 256];           // h sequence of current layer
__device__ __nv_bfloat16 g_Ahi[MTOT * 256];    // bf16 split of GEMM A operand
__device__ __nv_bfloat16 g_Alo[MTOT * 256];
__device__ __nv_bfloat16 g_Wthi[458752];       // transposed W (all 3 layers), hi
__device__ __nv_bfloat16 g_Wtlo[458752];       // lo
__device__ unsigned int g_bar_cnt;
__device__ unsigned int g_bar_gen;

// Wt layer offsets: L0 [1024][64], L1 [1024][256], L2 [512][256]
#define WOFF0 0
#define WOFF1 (1024 * 64)
#define WOFF2 (1024 * 64 + 1024 * 256)

// ---------------------------------------------------------------------------
// sm_100-safe helpers (NO tcgen05/TMEM — harness compiles for plain sm_100)
// ---------------------------------------------------------------------------
__device__ __forceinline__ uint32_t smem_u32(const void* p) {
    uint32_t a;
    asm("{ .reg .u64 t; cvta.to.shared.u64 t, %1; cvt.u32.u64 %0, t; }"
        : "=r"(a) : "l"(p));
    return a;
}

__device__ __forceinline__ void ldsm_x4(uint32_t* r, uint32_t addr) {
    asm volatile("ldmatrix.sync.aligned.m8n8.x4.shared.b16 {%0,%1,%2,%3}, [%4];"
                 : "=r"(r[0]), "=r"(r[1]), "=r"(r[2]), "=r"(r[3]) : "r"(addr));
}
__device__ __forceinline__ void ldsm_x2(uint32_t* r, uint32_t addr) {
    asm volatile("ldmatrix.sync.aligned.m8n8.x2.shared.b16 {%0,%1}, [%2];"
                 : "=r"(r[0]), "=r"(r[1]) : "r"(addr));
}
// D += A(16x16 bf16, row) * B(16x8 bf16, col); fp32 accum
__device__ __forceinline__ void mma_16816(float* d, const uint32_t* a, const uint32_t* b) {
    asm volatile(
        "mma.sync.aligned.m16n8k16.row.col.f32.bf16.bf16.f32 "
        "{%0,%1,%2,%3}, {%4,%5,%6,%7}, {%8,%9}, {%0,%1,%2,%3};\n"
        : "+f"(d[0]), "+f"(d[1]), "+f"(d[2]), "+f"(d[3])
        : "r"(a[0]), "r"(a[1]), "r"(a[2]), "r"(a[3]), "r"(b[0]), "r"(b[1]));
}

// ---------------------------------------------------------------------------
// bf16 split-conversion kernels
// ---------------------------------------------------------------------------
__global__ void conv_split(const float* __restrict__ in,
                           __nv_bfloat16* __restrict__ hi,
                           __nv_bfloat16* __restrict__ lo, int n4)
{
    int i = blockIdx.x * blockDim.x + threadIdx.x;
    if (i >= n4) return;
    float4 v = ((const float4*)in)[i];
    union { __nv_bfloat16 b[4]; uint2 u; } H, L;
    H.b[0] = __float2bfloat16_rn(v.x);
    H.b[1] = __float2bfloat16_rn(v.y);
    H.b[2] = __float2bfloat16_rn(v.z);
    H.b[3] = __float2bfloat16_rn(v.w);
    L.b[0] = __float2bfloat16_rn(v.x - __bfloat162float(H.b[0]));
    L.b[1] = __float2bfloat16_rn(v.y - __bfloat162float(H.b[1]));
    L.b[2] = __float2bfloat16_rn(v.z - __bfloat162float(H.b[2]));
    L.b[3] = __float2bfloat16_rn(v.w - __bfloat162float(H.b[3]));
    ((uint2*)hi)[i] = H.u;
    ((uint2*)lo)[i] = L.u;
}

// Transpose + split: Wt[n][k] = W[k][n]
__global__ void conv_w(const float* __restrict__ W,
                       __nv_bfloat16* __restrict__ hi,
                       __nv_bfloat16* __restrict__ lo, int K, int N)
{
    int idx = blockIdx.x * blockDim.x + threadIdx.x;
    if (idx >= N * K) return;
    int n = idx / K, k = idx - n * K;
    float v = W[(size_t)k * N + n];
    __nv_bfloat16 h = __float2bfloat16_rn(v);
    hi[idx] = h;
    lo[idx] = __float2bfloat16_rn(v - __bfloat162float(h));
}

// ---------------------------------------------------------------------------
// mma.sync GEMM: C[M,N] = (Ahi+Alo)[M,K] @ (Bhi+Blo)^T[N,K] + bias
// CTA tile 128x128, 8 warps (warp tile 64x32), BK=64 chunks.
// 3-term bf16 split: Ahi*Bhi + Ahi*Blo + Alo*Bhi, fp32 accumulators.
// Smem tiles [128][72] bf16 (stride 144B -> conflict-free ldmatrix).
// ---------------------------------------------------------------------------
#define TSTRIDE 72
#define TILE_B  (128 * TSTRIDE * 2)       // bytes per tile (18432)
#define GEMM_SMEM (4 * TILE_B)            // 73728

__global__ __launch_bounds__(256)
void mma_gemm(const __nv_bfloat16* __restrict__ Ahi, const __nv_bfloat16* __restrict__ Alo,
              const __nv_bfloat16* __restrict__ Bhi, const __nv_bfloat16* __restrict__ Blo,
              const float* __restrict__ bias, float* __restrict__ C, int K, int N)
{
    extern __shared__ __nv_bfloat16 sm[];
    __nv_bfloat16* sAhi = sm;
    __nv_bfloat16* sAlo = sm + 128 * TSTRIDE;
    __nv_bfloat16* sBhi = sm + 2 * 128 * TSTRIDE;
    __nv_bfloat16* sBlo = sm + 3 * 128 * TSTRIDE;
    const uint32_t uAhi = smem_u32(sAhi), uAlo = smem_u32(sAlo);
    const uint32_t uBhi = smem_u32(sBhi), uBlo = smem_u32(sBlo);

    const int tid = threadIdx.x;
    const int wid = tid >> 5, lane = tid & 31;
    const int warp_m = wid & 1, warp_n = wid >> 1;       // 2 x 4 warp grid
    const int bm = blockIdx.y * 128, bn = blockIdx.x * 128;

    float acc[4][4][4];                                   // [mi][ni][frag]
#pragma unroll
    for (int mi = 0; mi < 4; mi++)
#pragma unroll
        for (int ni = 0; ni < 4; ni++)
#pragma unroll
            for (int f = 0; f < 4; f++) acc[mi][ni][f] = 0.f;

    // ldmatrix lane addressing precompute
    const int r8  = lane & 7;
    const int grp = lane >> 3;                // 0..3 (A x4)
    const int aRowOff = ((grp & 1) ? 8 : 0) + r8;
    const int aColOff = (grp & 2) ? 8 : 0;
    const int bSel = grp & 1;                 // (B x2: lanes 0-15 used)

    const int nchunk = K >> 6;
    for (int c = 0; c < nchunk; c++) {
        const int k0g = c << 6;
        // Load 4 tiles [128 rows x 64 bf16]; 1024 uint4 per tile, 256 thr x 4.
#pragma unroll
        for (int i = 0; i < 4; i++) {
            int idx = tid + i * 256;
            int row = idx >> 3, seg = idx & 7;
            size_t ga = (size_t)(bm + row) * K + k0g + seg * 8;
            size_t gb = (size_t)(bn + row) * K + k0g + seg * 8;
            int so = row * TSTRIDE + seg * 8;
            *(uint4*)(sAhi + so) = *(const uint4*)&Ahi[ga];
            *(uint4*)(sAlo + so) = *(const uint4*)&Alo[ga];
            *(uint4*)(sBhi + so) = *(const uint4*)&Bhi[gb];
            *(uint4*)(sBlo + so) = *(const uint4*)&Blo[gb];
        }
        __syncthreads();

#pragma unroll
        for (int ks = 0; ks < 4; ks++) {
            const int k0 = ks * 16;
            uint32_t aHi[4][4], aLo[4][4], bHi[4][2], bLo[4][2];
#pragma unroll
            for (int mi = 0; mi < 4; mi++) {
                int row = warp_m * 64 + mi * 16 + aRowOff;
                uint32_t off = (uint32_t)(row * TSTRIDE + k0 + aColOff) * 2;
                ldsm_x4(aHi[mi], uAhi + off);
                ldsm_x4(aLo[mi], uAlo + off);
            }
#pragma unroll
            for (int ni = 0; ni < 4; ni++) {
                int row = warp_n * 32 + ni * 8 + r8;
                uint32_t off = (uint32_t)(row * TSTRIDE + k0 + bSel * 8) * 2;
                ldsm_x2(bHi[ni], uBhi + off);
                ldsm_x2(bLo[ni], uBlo + off);
            }
#pragma unroll
            for (int mi = 0; mi < 4; mi++)
#pragma unroll
                for (int ni = 0; ni < 4; ni++) {
                    mma_16816(acc[mi][ni], aHi[mi], bHi[ni]);
                    mma_16816(acc[mi][ni], aHi[mi], bLo[ni]);
                    mma_16816(acc[mi][ni], aLo[mi], bHi[ni]);
                }
        }
        __syncthreads();
    }

    // Epilogue: D frag (tg = lane>>2 row, tp = lane&3 col-pair) + bias
    const int tg = lane >> 2, tp = lane & 3;
#pragma unroll
    for (int mi = 0; mi < 4; mi++) {
#pragma unroll
        for (int ni = 0; ni < 4; ni++) {
            int col = bn + warp_n * 32 + ni * 8 + tp * 2;
            int row0 = bm + warp_m * 64 + mi * 16 + tg;
            float2 o0, o1;
            o0.x = acc[mi][ni][0] + bias[col];
            o0.y = acc[mi][ni][1] + bias[col + 1];
            o1.x = acc[mi][ni][2] + bias[col];
            o1.y = acc[mi][ni][3] + bias[col + 1];
            *(float2*)&C[(size_t)row0 * N + col] = o0;
            *(float2*)&C[(size_t)(row0 + 8) * N + col] = o1;
        }
    }
}

// ---------------------------------------------------------------------------
// Software grid barrier (persistent kernels, 1 CTA/SM, fixed small backoff)
// ---------------------------------------------------------------------------
__device__ __forceinline__ void grid_barrier() {
    __syncthreads();
    if (threadIdx.x == 0) {
        __threadfence();
        unsigned int gen = *(volatile unsigned int*)&g_bar_gen;
        unsigned int arr = atomicAdd(&g_bar_cnt, 1u);
        if (arr == gridDim.x - 1u) {
            g_bar_cnt = 0u;
            __threadfence();
            atomicAdd(&g_bar_gen, 1u);
        } else {
            while (*(volatile unsigned int*)&g_bar_gen == gen) {
                __nanosleep(64);
            }
        }
        __threadfence();
    }
    __syncthreads();
}

// ---------------------------------------------------------------------------
// Persistent LSTM recurrence. 256 threads (8 warps = 2/SMSP for latency
// hiding). Grid = (B/(32*RPT)) x (H/8) = 128 CTAs. Thread owns RPT batch
// rows x 1 column; c-state in regs; U slice (32KB max) in smem.
// Keras gate order [i|f|g|o]; c = f*c + i*g; h = o*tanh(c).
// ---------------------------------------------------------------------------
__device__ __forceinline__ float sigmoidf_(float x) {
    return 1.f / (1.f + __expf(-x));
}

template<int H, int RPT>
__global__ __launch_bounds__(256, 1)
void lstm_kernel(const float* __restrict__ xW, const float* __restrict__ U,
                 float* __restrict__ hseq)
{
    constexpr int K = H;
    constexpr int KP = K + 4;
    constexpr int FOURH = 4 * H;
    constexpr int NCB = H / 8;
    constexpr int BB = 32 * RPT;

    __shared__ float Us[4 * 8 * KP];

    const int bx = blockIdx.x;
    const int cb = bx % NCB;
    const int bb = bx / NCB;
    const int tid = threadIdx.x;
    const int cc = tid & 7;
    const int bg = tid >> 3;           // 0..31
    const int c0 = cb * 8;
    const int b0 = bb * BB + bg * RPT;

    for (int idx = tid; idx < 4 * 8 * K; idx += 256) {
        int col = idx & 7;
        int k = (idx >> 3) % K;
        int g = idx / (8 * K);
        Us[(g * 8 + col) * KP + k] = U[(size_t)k * FOURH + g * H + c0 + col];
    }
    __syncthreads();

    const float* UsI = &Us[(0 * 8 + cc) * KP];
    const float* UsF = &Us[(1 * 8 + cc) * KP];
    const float* UsG = &Us[(2 * 8 + cc) * KP];
    const float* UsO = &Us[(3 * 8 + cc) * KP];

    float cst[RPT];
#pragma unroll
    for (int i = 0; i < RPT; i++) cst[i] = 0.f;

    for (int t = 0; t < TLEN; t++) {
        float acc[4][RPT];
#pragma unroll
        for (int i = 0; i < RPT; i++) {
            const float* xwrow = &xW[((size_t)(b0 + i) * TLEN + t) * FOURH + c0 + cc];
            acc[0][i] = xwrow[0 * H];
            acc[1][i] = xwrow[1 * H];
            acc[2][i] = xwrow[2 * H];
            acc[3][i] = xwrow[3 * H];
        }

        if (t > 0) {
            const float* hbase = &hseq[((size_t)b0 * TLEN + (t - 1)) * H];
#pragma unroll 2
            for (int k = 0; k < K; k += 4) {
                float4 ui = *(const float4*)(UsI + k);
                float4 uf = *(const float4*)(UsF + k);
                float4 ug = *(const float4*)(UsG + k);
                float4 uo = *(const float4*)(UsO + k);
#pragma unroll
                for (int i = 0; i < RPT; i++) {
                    float4 hv = *(const float4*)(hbase + (size_t)i * TLEN * H + k);
                    acc[0][i] = fmaf(hv.x, ui.x, acc[0][i]);
                    acc[0][i] = fmaf(hv.y, ui.y, acc[0][i]);
                    acc[0][i] = fmaf(hv.z, ui.z, acc[0][i]);
                    acc[0][i] = fmaf(hv.w, ui.w, acc[0][i]);
                    acc[1][i] = fmaf(hv.x, uf.x, acc[1][i]);
                    acc[1][i] = fmaf(hv.y, uf.y, acc[1][i]);
                    acc[1][i] = fmaf(hv.z, uf.z, acc[1][i]);
                    acc[1][i] = fmaf(hv.w, uf.w, acc[1][i]);
                    acc[2][i] = fmaf(hv.x, ug.x, acc[2][i]);
                    acc[2][i] = fmaf(hv.y, ug.y, acc[2][i]);
                    acc[2][i] = fmaf(hv.z, ug.z, acc[2][i]);
                    acc[2][i] = fmaf(hv.w, ug.w, acc[2][i]);
                    acc[3][i] = fmaf(hv.x, uo.x, acc[3][i]);
                    acc[3][i] = fmaf(hv.y, uo.y, acc[3][i]);
                    acc[3][i] = fmaf(hv.z, uo.z, acc[3][i]);
                    acc[3][i] = fmaf(hv.w, uo.w, acc[3][i]);
                }
            }
        }

#pragma unroll
        for (int i = 0; i < RPT; i++) {
            float ig = sigmoidf_(acc[0][i]);
            float fg = sigmoidf_(acc[1][i]);
            float gg = tanhf(acc[2][i]);
            float og = sigmoidf_(acc[3][i]);
            float cn = (t == 0) ? ig * gg : fmaf(fg, cst[i], ig * gg);
            cst[i] = cn;
            float hn = og * tanhf(cn);
            hseq[((size_t)(b0 + i) * TLEN + t) * H + c0 + cc] = hn;
        }

        if (t < TLEN - 1) grid_barrier();
    }
}

// ---------------------------------------------------------------------------
// Final dense: out[b,d] = hseq[b, T-1, :128] @ Wd[128,64] + bd[64]
// ---------------------------------------------------------------------------
__global__ void dense_kernel(const float* __restrict__ hseq,
                             const float* __restrict__ Wd,
                             const float* __restrict__ bd,
                             float* __restrict__ out)
{
    int b = blockIdx.x;
    int d = threadIdx.x;
    const float* h = &hseq[((size_t)b * TLEN + (TLEN - 1)) * 128];
    float acc = 0.f;
#pragma unroll 4
    for (int k = 0; k < 128; k++)
        acc = fmaf(h[k], Wd[k * 64 + d], acc);
    out[b * 64 + d] = acc + bd[d];
}

// ---------------------------------------------------------------------------
// Launch sequence
// ---------------------------------------------------------------------------
extern "C" void kernel_launch(void* const* d_in, const int* in_sizes, int n_in,
                              void* d_out, int out_size)
{
    (void)in_sizes; (void)n_in; (void)out_size;
    const float* x  = (const float*)d_in[0];
    const float* W0 = (const float*)d_in[1];
    const float* U0 = (const float*)d_in[2];
    const float* b0 = (const float*)d_in[3];
    const float* W1 = (const float*)d_in[4];
    const float* U1 = (const float*)d_in[5];
    const float* b1 = (const float*)d_in[6];
    const float* W2 = (const float*)d_in[7];
    const float* U2 = (const float*)d_in[8];
    const float* b2 = (const float*)d_in[9];
    const float* Wd = (const float*)d_in[10];
    const float* bd = (const float*)d_in[11];
    float* out = (float*)d_out;

    void* p;
    cudaGetSymbolAddress(&p, g_xW);   float* xw = (float*)p;
    cudaGetSymbolAddress(&p, g_hseq); float* hs = (float*)p;
    cudaGetSymbolAddress(&p, g_Ahi);  __nv_bfloat16* ahi = (__nv_bfloat16*)p;
    cudaGetSymbolAddress(&p, g_Alo);  __nv_bfloat16* alo = (__nv_bfloat16*)p;
    cudaGetSymbolAddress(&p, g_Wthi); __nv_bfloat16* whi = (__nv_bfloat16*)p;
    cudaGetSymbolAddress(&p, g_Wtlo); __nv_bfloat16* wlo = (__nv_bfloat16*)p;

    cudaFuncSetAttribute(mma_gemm, cudaFuncAttributeMaxDynamicSharedMemorySize, GEMM_SMEM);

    // Weight transpose+split (tiny; runs every replay — deterministic)
    conv_w<<<(1024 * 64  + 255) / 256, 256>>>(W0, whi + WOFF0, wlo + WOFF0, 64,  1024);
    conv_w<<<(1024 * 256 + 255) / 256, 256>>>(W1, whi + WOFF1, wlo + WOFF1, 256, 1024);
    conv_w<<<(512  * 256 + 255) / 256, 256>>>(W2, whi + WOFF2, wlo + WOFF2, 256, 512);

    // Layer 0
    conv_split<<<(MTOT * 64 / 4 + 255) / 256, 256>>>(x, ahi, alo, MTOT * 64 / 4);
    mma_gemm<<<dim3(8, MTOT / 128), 256, GEMM_SMEM>>>(ahi, alo, whi + WOFF0, wlo + WOFF0,
                                                      b0, xw, 64, 1024);
    lstm_kernel<256, 2><<<128, 256>>>(xw, U0, hs);

    // Layer 1
    conv_split<<<(MTOT * 256 / 4 + 255) / 256, 256>>>(hs, ahi, alo, MTOT * 256 / 4);
    mma_gemm<<<dim3(8, MTOT / 128), 256, GEMM_SMEM>>>(ahi, alo, whi + WOFF1, wlo + WOFF1,
                                                      b1, xw, 256, 1024);
    lstm_kernel<256, 2><<<128, 256>>>(xw, U1, hs);

    // Layer 2
    conv_split<<<(MTOT * 256 / 4 + 255) / 256, 256>>>(hs, ahi, alo, MTOT * 256 / 4);
    mma_gemm<<<dim3(4, MTOT / 128), 256, GEMM_SMEM>>>(ahi, alo, whi + WOFF2, wlo + WOFF2,
                                                      b2, xw, 256, 512);
    lstm_kernel<128, 1><<<128, 256>>>(xw, U2, hs);

    // Dense head
    dense_kernel<<<BSZ, 64>>>(hs, Wd, bd, out);
}

// round 6
// speedup vs baseline: 2.1055x; 1.6883x over previous
#include <cuda_runtime.h>
#include <cuda_bf16.h>
#include <cstdint>
#include <cstddef>

#define BSZ  256
#define TLEN 512
#define DIN  64
#define MTOT (BSZ * TLEN)

typedef __nv_bfloat16 bf16;

// ---------------------------------------------------------------------------
// Device-global scratch (allocation-free per harness rules)
// ---------------------------------------------------------------------------
__device__ float g_xW[MTOT * 1024];          // xW = x@W + b (largest layer)
__device__ bf16  g_Ahi[MTOT * 256];          // A operand hi (x split, then h)
__device__ bf16  g_Alo[MTOT * 256];          // A operand lo
__device__ bf16  g_Wthi[458752];             // W^T (all 3 layers), hi
__device__ bf16  g_Wtlo[458752];
__device__ bf16  g_Uthi[589824];             // U^T (all 3 layers), hi
__device__ bf16  g_Utlo[589824];
__device__ unsigned int g_bar_cnt;
__device__ unsigned int g_bar_gen;

#define WOFF0 0
#define WOFF1 (1024 * 64)
#define WOFF2 (1024 * 64 + 1024 * 256)
#define UOFF0 0
#define UOFF1 (1024 * 256)
#define UOFF2 (2 * 1024 * 256)

// ---------------------------------------------------------------------------
// sm_100-safe helpers (ldmatrix + mma.sync only; no tcgen05)
// ---------------------------------------------------------------------------
__device__ __forceinline__ uint32_t smem_u32(const void* p) {
    uint32_t a;
    asm("{ .reg .u64 t; cvta.to.shared.u64 t, %1; cvt.u32.u64 %0, t; }"
        : "=r"(a) : "l"(p));
    return a;
}
__device__ __forceinline__ void ldsm_x4(uint32_t* r, uint32_t addr) {
    asm volatile("ldmatrix.sync.aligned.m8n8.x4.shared.b16 {%0,%1,%2,%3}, [%4];"
                 : "=r"(r[0]), "=r"(r[1]), "=r"(r[2]), "=r"(r[3]) : "r"(addr));
}
__device__ __forceinline__ void ldsm_x2(uint32_t* r, uint32_t addr) {
    asm volatile("ldmatrix.sync.aligned.m8n8.x2.shared.b16 {%0,%1}, [%2];"
                 : "=r"(r[0]), "=r"(r[1]) : "r"(addr));
}
__device__ __forceinline__ void mma_16816(float* d, const uint32_t* a, const uint32_t* b) {
    asm volatile(
        "mma.sync.aligned.m16n8k16.row.col.f32.bf16.bf16.f32 "
        "{%0,%1,%2,%3}, {%4,%5,%6,%7}, {%8,%9}, {%0,%1,%2,%3};\n"
        : "+f"(d[0]), "+f"(d[1]), "+f"(d[2]), "+f"(d[3])
        : "r"(a[0]), "r"(a[1]), "r"(a[2]), "r"(a[3]), "r"(b[0]), "r"(b[1]));
}

__device__ __forceinline__ float sigf(float x) {
    return __fdividef(1.f, 1.f + __expf(-x));
}
__device__ __forceinline__ float tanhf_(float x) {
    return 1.f - __fdividef(2.f, 1.f + __expf(2.f * x));
}

// ---------------------------------------------------------------------------
// Conversion kernels
// ---------------------------------------------------------------------------
__global__ void conv_split(const float* __restrict__ in,
                           bf16* __restrict__ hi, bf16* __restrict__ lo, int n4)
{
    int i = blockIdx.x * blockDim.x + threadIdx.x;
    if (i >= n4) return;
    float4 v = ((const float4*)in)[i];
    union { bf16 b[4]; uint2 u; } H, L;
    H.b[0] = __float2bfloat16_rn(v.x);
    H.b[1] = __float2bfloat16_rn(v.y);
    H.b[2] = __float2bfloat16_rn(v.z);
    H.b[3] = __float2bfloat16_rn(v.w);
    L.b[0] = __float2bfloat16_rn(v.x - __bfloat162float(H.b[0]));
    L.b[1] = __float2bfloat16_rn(v.y - __bfloat162float(H.b[1]));
    L.b[2] = __float2bfloat16_rn(v.z - __bfloat162float(H.b[2]));
    L.b[3] = __float2bfloat16_rn(v.w - __bfloat162float(H.b[3]));
    ((uint2*)hi)[i] = H.u;
    ((uint2*)lo)[i] = L.u;
}

// Transpose + split: T[n][k] = M[k][n] (used for both W and U)
__global__ void conv_w(const float* __restrict__ W,
                       bf16* __restrict__ hi, bf16* __restrict__ lo, int K, int N)
{
    int idx = blockIdx.x * blockDim.x + threadIdx.x;
    if (idx >= N * K) return;
    int n = idx / K, k = idx - n * K;
    float v = W[(size_t)k * N + n];
    bf16 h = __float2bfloat16_rn(v);
    hi[idx] = h;
    lo[idx] = __float2bfloat16_rn(v - __bfloat162float(h));
}

// ---------------------------------------------------------------------------
// mma.sync GEMM (proven R5): C[M,N] = (Ahi+Alo)@(Bhi+Blo)^T + bias
// ---------------------------------------------------------------------------
#define TSTRIDE 72
#define GEMM_SMEM (4 * 128 * TSTRIDE * 2)

__global__ __launch_bounds__(256)
void mma_gemm(const bf16* __restrict__ Ahi, const bf16* __restrict__ Alo,
              const bf16* __restrict__ Bhi, const bf16* __restrict__ Blo,
              const float* __restrict__ bias, float* __restrict__ C, int K, int N)
{
    extern __shared__ bf16 sm[];
    bf16* sAhi = sm;
    bf16* sAlo = sm + 128 * TSTRIDE;
    bf16* sBhi = sm + 2 * 128 * TSTRIDE;
    bf16* sBlo = sm + 3 * 128 * TSTRIDE;
    const uint32_t uAhi = smem_u32(sAhi), uAlo = smem_u32(sAlo);
    const uint32_t uBhi = smem_u32(sBhi), uBlo = smem_u32(sBlo);

    const int tid = threadIdx.x;
    const int wid = tid >> 5, lane = tid & 31;
    const int warp_m = wid & 1, warp_n = wid >> 1;
    const int bm = blockIdx.y * 128, bn = blockIdx.x * 128;

    float acc[4][4][4];
#pragma unroll
    for (int mi = 0; mi < 4; mi++)
#pragma unroll
        for (int ni = 0; ni < 4; ni++)
#pragma unroll
            for (int f = 0; f < 4; f++) acc[mi][ni][f] = 0.f;

    const int r8  = lane & 7;
    const int grp = lane >> 3;
    const int aRowOff = ((grp & 1) ? 8 : 0) + r8;
    const int aColOff = (grp & 2) ? 8 : 0;
    const int bSel = grp & 1;

    const int nchunk = K >> 6;
    for (int c = 0; c < nchunk; c++) {
        const int k0g = c << 6;
#pragma unroll
        for (int i = 0; i < 4; i++) {
            int idx = tid + i * 256;
            int row = idx >> 3, seg = idx & 7;
            size_t ga = (size_t)(bm + row) * K + k0g + seg * 8;
            size_t gb = (size_t)(bn + row) * K + k0g + seg * 8;
            int so = row * TSTRIDE + seg * 8;
            *(uint4*)(sAhi + so) = *(const uint4*)&Ahi[ga];
            *(uint4*)(sAlo + so) = *(const uint4*)&Alo[ga];
            *(uint4*)(sBhi + so) = *(const uint4*)&Bhi[gb];
            *(uint4*)(sBlo + so) = *(const uint4*)&Blo[gb];
        }
        __syncthreads();

#pragma unroll
        for (int ks = 0; ks < 4; ks++) {
            const int k0 = ks * 16;
            uint32_t aHi[4][4], aLo[4][4], bHi[4][2], bLo[4][2];
#pragma unroll
            for (int mi = 0; mi < 4; mi++) {
                int row = warp_m * 64 + mi * 16 + aRowOff;
                uint32_t off = (uint32_t)(row * TSTRIDE + k0 + aColOff) * 2;
                ldsm_x4(aHi[mi], uAhi + off);
                ldsm_x4(aLo[mi], uAlo + off);
            }
#pragma unroll
            for (int ni = 0; ni < 4; ni++) {
                int row = warp_n * 32 + ni * 8 + r8;
                uint32_t off = (uint32_t)(row * TSTRIDE + k0 + bSel * 8) * 2;
                ldsm_x2(bHi[ni], uBhi + off);
                ldsm_x2(bLo[ni], uBlo + off);
            }
#pragma unroll
            for (int mi = 0; mi < 4; mi++)
#pragma unroll
                for (int ni = 0; ni < 4; ni++) {
                    mma_16816(acc[mi][ni], aHi[mi], bHi[ni]);
                    mma_16816(acc[mi][ni], aHi[mi], bLo[ni]);
                    mma_16816(acc[mi][ni], aLo[mi], bHi[ni]);
                }
        }
        __syncthreads();
    }

    const int tg = lane >> 2, tp = lane & 3;
#pragma unroll
    for (int mi = 0; mi < 4; mi++) {
#pragma unroll
        for (int ni = 0; ni < 4; ni++) {
            int col = bn + warp_n * 32 + ni * 8 + tp * 2;
            int row0 = bm + warp_m * 64 + mi * 16 + tg;
            float2 o0, o1;
            o0.x = acc[mi][ni][0] + bias[col];
            o0.y = acc[mi][ni][1] + bias[col + 1];
            o1.x = acc[mi][ni][2] + bias[col];
            o1.y = acc[mi][ni][3] + bias[col + 1];
            *(float2*)&C[(size_t)row0 * N + col] = o0;
            *(float2*)&C[(size_t)(row0 + 8) * N + col] = o1;
        }
    }
}

// ---------------------------------------------------------------------------
// Software grid barrier (persistent kernels, <=128 CTAs, 1/SM)
// ---------------------------------------------------------------------------
__device__ __forceinline__ void grid_barrier() {
    __syncthreads();
    if (threadIdx.x == 0) {
        __threadfence();
        unsigned int gen = *(volatile unsigned int*)&g_bar_gen;
        unsigned int arr = atomicAdd(&g_bar_cnt, 1u);
        if (arr == gridDim.x - 1u) {
            g_bar_cnt = 0u;
            __threadfence();
            atomicAdd(&g_bar_gen, 1u);
        } else {
            while (*(volatile unsigned int*)&g_bar_gen == gen) {
                __nanosleep(64);
            }
        }
        __threadfence();
    }
    __syncthreads();
}

// ---------------------------------------------------------------------------
// Tensor-core LSTM recurrence (persistent, 128 CTAs, 256 threads).
// Grid: 8 batch-blocks (32 rows) x 16 unit-blocks (UPC = H/16 units).
// Packed cols per CTA: PC = 4*UPC, unit-major packing p = u*4 + g so one
// lane-pair (tp, tp^1) owns all 4 gates of a unit -> c-state in registers,
// one shfl_xor(1) exchange. z = xW + h@U via 3-term bf16-split mma.sync.
// U^T slice in smem (hi frags hoisted to regs); h staged to smem per step;
// h written to global as bf16 hi/lo = next layer's GEMM A operand.
// ---------------------------------------------------------------------------
template<int H>
__global__ __launch_bounds__(256, 1)
void lstm_mma(const float* __restrict__ xW,
              const bf16* __restrict__ Uthi, const bf16* __restrict__ Utlo,
              bf16* __restrict__ Hhi, bf16* __restrict__ Hlo)
{
    constexpr int K    = H;
    constexpr int KS   = K / 16;       // k-steps
    constexpr int UPC  = H / 16;       // units per CTA
    constexpr int PC   = 4 * UPC;      // packed cols per CTA
    constexpr int WN   = PC / 4;       // warp n-tile
    constexpr int NI   = WN / 8;       // 8-col groups per warp
    constexpr int KS2  = K + 8;        // smem stride (elems); row=16B aligned
    constexpr int FOURH = 4 * H;
    constexpr int U4R  = K / 8;        // uint4 per row

    extern __shared__ bf16 dyn[];
    bf16* sUhi = dyn;
    bf16* sUlo = dyn + PC * KS2;
    bf16* sHhi = dyn + 2 * PC * KS2;
    bf16* sHlo = dyn + 2 * PC * KS2 + 32 * KS2;
    const uint32_t uUhi = smem_u32(sUhi), uUlo = smem_u32(sUlo);
    const uint32_t uHhi = smem_u32(sHhi), uHlo = smem_u32(sHlo);

    const int tid = threadIdx.x;
    const int wid = tid >> 5, lane = tid & 31;
    const int wm = wid & 1, wn = wid >> 1;
    const int cb = blockIdx.x & 15;        // unit block
    const int bb = blockIdx.x >> 4;        // batch block
    const int b0 = bb * 32;

    const int r8  = lane & 7;
    const int grp = lane >> 3;
    const int aRowOff = ((grp & 1) ? 8 : 0) + r8;
    const int aColOff = (grp & 2) ? 8 : 0;
    const int bSel = grp & 1;
    const int tg = lane >> 2, tp = lane & 3;
    const bool evenp = (tp & 1) == 0;

    // Load persistent U^T slice: row p -> global n = (p&3)*H + cb*UPC + (p>>2)
    for (int idx = tid; idx < PC * U4R; idx += 256) {
        int p = idx / U4R, q = idx - p * U4R;
        int n = (p & 3) * H + cb * UPC + (p >> 2);
        *(uint4*)(sUhi + p * KS2 + q * 8) = *(const uint4*)&Uthi[(size_t)n * K + q * 8];
        *(uint4*)(sUlo + p * KS2 + q * 8) = *(const uint4*)&Utlo[(size_t)n * K + q * 8];
    }
    __syncthreads();

    // Hoist B-hi fragments (step-invariant) into registers
    uint32_t bHi[KS][NI][2];
#pragma unroll
    for (int ks = 0; ks < KS; ks++)
#pragma unroll
        for (int ni = 0; ni < NI; ni++) {
            uint32_t off = (uint32_t)((wn * WN + ni * 8 + r8) * KS2 + ks * 16 + bSel * 8) * 2;
            ldsm_x2(bHi[ks][ni], uUhi + off);
        }

    // Per-thread epilogue addressing
    const int rA = b0 + wm * 16 + tg;                      // row 0 (row 1 = +8)
    int colg[NI][2];
#pragma unroll
    for (int ni = 0; ni < NI; ni++)
#pragma unroll
        for (int j = 0; j < 2; j++) {
            int p = wn * WN + ni * 8 + 2 * tp + j;
            colg[ni][j] = (p & 3) * H + cb * UPC + (p >> 2);
        }
    int uG[NI];
#pragma unroll
    for (int ni = 0; ni < NI; ni++)
        uG[ni] = cb * UPC + ((wn * WN + ni * 8 + 2 * tp) >> 2);

    float cst[NI][2];
#pragma unroll
    for (int ni = 0; ni < NI; ni++) { cst[ni][0] = 0.f; cst[ni][1] = 0.f; }

    const size_t xw0 = (size_t)rA * TLEN * FOURH;
    const size_t xw1 = (size_t)(rA + 8) * TLEN * FOURH;

    for (int t = 0; t < TLEN; t++) {
        // acc init from xW (bias included)
        float acc[NI][4];
        const float* x0 = xW + xw0 + (size_t)t * FOURH;
        const float* x1 = xW + xw1 + (size_t)t * FOURH;
#pragma unroll
        for (int ni = 0; ni < NI; ni++) {
            acc[ni][0] = x0[colg[ni][0]];
            acc[ni][1] = x0[colg[ni][1]];
            acc[ni][2] = x1[colg[ni][0]];
            acc[ni][3] = x1[colg[ni][1]];
        }

        if (t > 0) {
            // Stage h(t-1) tile [32 x K] hi/lo into smem
            for (int idx = tid; idx < 32 * U4R; idx += 256) {
                int r = idx / U4R, q = idx - r * U4R;
                size_t g = ((size_t)(b0 + r) * TLEN + (t - 1)) * H + q * 8;
                *(uint4*)(sHhi + r * KS2 + q * 8) = *(const uint4*)&Hhi[g];
                *(uint4*)(sHlo + r * KS2 + q * 8) = *(const uint4*)&Hlo[g];
            }
            __syncthreads();

#pragma unroll
            for (int ks = 0; ks < KS; ks++) {
                uint32_t ahi[4], alo[4];
                uint32_t aoff = (uint32_t)((wm * 16 + aRowOff) * KS2 + ks * 16 + aColOff) * 2;
                ldsm_x4(ahi, uHhi + aoff);
                ldsm_x4(alo, uHlo + aoff);
#pragma unroll
                for (int ni = 0; ni < NI; ni++) {
                    uint32_t blo[2];
                    uint32_t boff = (uint32_t)((wn * WN + ni * 8 + r8) * KS2 + ks * 16 + bSel * 8) * 2;
                    ldsm_x2(blo, uUlo + boff);
                    mma_16816(acc[ni], ahi, bHi[ks][ni]);
                    mma_16816(acc[ni], ahi, blo);
                    mma_16816(acc[ni], alo, bHi[ks][ni]);
                }
            }
        }

        // Gates: even tp holds (i,f), odd tp holds (g,o); exchange via shfl.
#pragma unroll
        for (int ni = 0; ni < NI; ni++) {
            float v0, v1, v2, v3;
            if (evenp) {
                v0 = sigf(acc[ni][0]); v1 = sigf(acc[ni][1]);
                v2 = sigf(acc[ni][2]); v3 = sigf(acc[ni][3]);
            } else {
                v0 = tanhf_(acc[ni][0]); v1 = sigf(acc[ni][1]);
                v2 = tanhf_(acc[ni][2]); v3 = sigf(acc[ni][3]);
            }
            float p0 = __shfl_xor_sync(0xffffffffu, v0, 1);
            float p1 = __shfl_xor_sync(0xffffffffu, v1, 1);
            float p2 = __shfl_xor_sync(0xffffffffu, v2, 1);
            float p3 = __shfl_xor_sync(0xffffffffu, v3, 1);
            float i0 = evenp ? v0 : p0, f0 = evenp ? v1 : p1;
            float g0 = evenp ? p0 : v0, o0 = evenp ? p1 : v1;
            float i1 = evenp ? v2 : p2, f1 = evenp ? v3 : p3;
            float g1 = evenp ? p2 : v2, o1 = evenp ? p3 : v3;

            float c0 = fmaf(f0, cst[ni][0], i0 * g0);
            float c1 = fmaf(f1, cst[ni][1], i1 * g1);
            cst[ni][0] = c0;
            cst[ni][1] = c1;
            float h0 = o0 * tanhf_(c0);
            float h1 = o1 * tanhf_(c1);

            if (evenp) {
                bf16 h0h = __float2bfloat16_rn(h0);
                bf16 h1h = __float2bfloat16_rn(h1);
                size_t a0 = ((size_t)rA * TLEN + t) * H + uG[ni];
                size_t a1 = ((size_t)(rA + 8) * TLEN + t) * H + uG[ni];
                Hhi[a0] = h0h;
                Hlo[a0] = __float2bfloat16_rn(h0 - __bfloat162float(h0h));
                Hhi[a1] = h1h;
                Hlo[a1] = __float2bfloat16_rn(h1 - __bfloat162float(h1h));
            }
        }

        if (t < TLEN - 1) grid_barrier();
    }
}

// ---------------------------------------------------------------------------
// Final dense: out[b,d] = (hi+lo)[b,T-1,:128] @ Wd + bd
// ---------------------------------------------------------------------------
__global__ void dense_kernel(const bf16* __restrict__ Hhi, const bf16* __restrict__ Hlo,
                             const float* __restrict__ Wd, const float* __restrict__ bd,
                             float* __restrict__ out)
{
    int b = blockIdx.x;
    int d = threadIdx.x;
    size_t base = ((size_t)b * TLEN + (TLEN - 1)) * 128;
    float acc = 0.f;
#pragma unroll 4
    for (int k = 0; k < 128; k++) {
        float h = __bfloat162float(Hhi[base + k]) + __bfloat162float(Hlo[base + k]);
        acc = fmaf(h, Wd[k * 64 + d], acc);
    }
    out[b * 64 + d] = acc + bd[d];
}

// ---------------------------------------------------------------------------
// Launch sequence
// ---------------------------------------------------------------------------
extern "C" void kernel_launch(void* const* d_in, const int* in_sizes, int n_in,
                              void* d_out, int out_size)
{
    (void)in_sizes; (void)n_in; (void)out_size;
    const float* x  = (const float*)d_in[0];
    const float* W0 = (const float*)d_in[1];
    const float* U0 = (const float*)d_in[2];
    const float* b0 = (const float*)d_in[3];
    const float* W1 = (const float*)d_in[4];
    const float* U1 = (const float*)d_in[5];
    const float* b1 = (const float*)d_in[6];
    const float* W2 = (const float*)d_in[7];
    const float* U2 = (const float*)d_in[8];
    const float* b2 = (const float*)d_in[9];
    const float* Wd = (const float*)d_in[10];
    const float* bd = (const float*)d_in[11];
    float* out = (float*)d_out;

    void* p;
    cudaGetSymbolAddress(&p, g_xW);   float* xw = (float*)p;
    cudaGetSymbolAddress(&p, g_Ahi);  bf16* ahi = (bf16*)p;
    cudaGetSymbolAddress(&p, g_Alo);  bf16* alo = (bf16*)p;
    cudaGetSymbolAddress(&p, g_Wthi); bf16* whi = (bf16*)p;
    cudaGetSymbolAddress(&p, g_Wtlo); bf16* wlo = (bf16*)p;
    cudaGetSymbolAddress(&p, g_Uthi); bf16* uhi = (bf16*)p;
    cudaGetSymbolAddress(&p, g_Utlo); bf16* ulo = (bf16*)p;

    cudaFuncSetAttribute(mma_gemm, cudaFuncAttributeMaxDynamicSharedMemorySize, GEMM_SMEM);
    // lstm_mma smem: H=256: (2*64+64)*264*2 = 101376 B; H=128: (2*32+64)*136*2 = 34816 B
    const int LS256 = (2 * 64 + 64) * 264 * 2;
    const int LS128 = (2 * 32 + 64) * 136 * 2;
    cudaFuncSetAttribute(lstm_mma<256>, cudaFuncAttributeMaxDynamicSharedMemorySize, LS256);
    cudaFuncSetAttribute(lstm_mma<128>, cudaFuncAttributeMaxDynamicSharedMemorySize, LS128);

    // Weight transposes + splits (W for GEMMs, U for recurrences)
    conv_w<<<(1024 * 64  + 255) / 256, 256>>>(W0, whi + WOFF0, wlo + WOFF0, 64,  1024);
    conv_w<<<(1024 * 256 + 255) / 256, 256>>>(W1, whi + WOFF1, wlo + WOFF1, 256, 1024);
    conv_w<<<(512  * 256 + 255) / 256, 256>>>(W2, whi + WOFF2, wlo + WOFF2, 256, 512);
    conv_w<<<(1024 * 256 + 255) / 256, 256>>>(U0, uhi + UOFF0, ulo + UOFF0, 256, 1024);
    conv_w<<<(1024 * 256 + 255) / 256, 256>>>(U1, uhi + UOFF1, ulo + UOFF1, 256, 1024);
    conv_w<<<(512  * 128 + 255) / 256, 256>>>(U2, uhi + UOFF2, ulo + UOFF2, 128, 512);

    // Layer 0: split x -> GEMM (K=64) -> recurrence (writes h as bf16 split)
    conv_split<<<(MTOT * 64 / 4 + 255) / 256, 256>>>(x, ahi, alo, MTOT * 64 / 4);
    mma_gemm<<<dim3(8, MTOT / 128), 256, GEMM_SMEM>>>(ahi, alo, whi + WOFF0, wlo + WOFF0,
                                                      b0, xw, 64, 1024);
    lstm_mma<256><<<128, 256, LS256>>>(xw, uhi + UOFF0, ulo + UOFF0, ahi, alo);

    // Layer 1: GEMM consumes h^0 split directly
    mma_gemm<<<dim3(8, MTOT / 128), 256, GEMM_SMEM>>>(ahi, alo, whi + WOFF1, wlo + WOFF1,
                                                      b1, xw, 256, 1024);
    lstm_mma<256><<<128, 256, LS256>>>(xw, uhi + UOFF1, ulo + UOFF1, ahi, alo);

    // Layer 2
    mma_gemm<<<dim3(4, MTOT / 128), 256, GEMM_SMEM>>>(ahi, alo, whi + WOFF2, wlo + WOFF2,
                                                      b2, xw, 256, 512);
    lstm_mma<128><<<128, 256, LS128>>>(xw, uhi + UOFF2, ulo + UOFF2, ahi, alo);

    // Dense head
    dense_kernel<<<BSZ, 64>>>(ahi, alo, Wd, bd, out);
}

// round 8
// speedup vs baseline: 2.5222x; 1.1979x over previous
#include <cuda_runtime.h>
#include <cuda_bf16.h>
#include <cstdint>
#include <cstddef>

#define BSZ  256
#define TLEN 512
#define DIN  64
#define MTOT (BSZ * TLEN)

typedef __nv_bfloat16 bf16;

// ---------------------------------------------------------------------------
// Device-global scratch
// ---------------------------------------------------------------------------
__device__ float g_xW[MTOT * 1024];          // xW = x@W + b, PACKED col order
__device__ bf16  g_Ahi[MTOT * 256];          // A operand hi (x split, then h)
__device__ bf16  g_Alo[MTOT * 256];
__device__ bf16  g_Wthi[458752];             // W^T packed (all 3 layers), hi
__device__ bf16  g_Wtlo[458752];
__device__ bf16  g_Uthi[589824];             // U^T packed (all 3 layers)
__device__ bf16  g_Utlo[589824];
__device__ float g_bias[1024];               // permuted bias (per-layer, reused)
__device__ unsigned int g_bcnt[8 * 32];      // per-batch-block barriers (padded)
__device__ unsigned int g_bgen[8 * 32];

#define WOFF0 0
#define WOFF1 (1024 * 64)
#define WOFF2 (1024 * 64 + 1024 * 256)
#define UOFF0 0
#define UOFF1 (1024 * 256)
#define UOFF2 (2 * 1024 * 256)

// ---------------------------------------------------------------------------
// sm_100-safe helpers (ldmatrix + mma.sync; no tcgen05)
// ---------------------------------------------------------------------------
__device__ __forceinline__ uint32_t smem_u32(const void* p) {
    uint32_t a;
    asm("{ .reg .u64 t; cvta.to.shared.u64 t, %1; cvt.u32.u64 %0, t; }"
        : "=r"(a) : "l"(p));
    return a;
}
__device__ __forceinline__ void ldsm_x4(uint32_t* r, uint32_t addr) {
    asm volatile("ldmatrix.sync.aligned.m8n8.x4.shared.b16 {%0,%1,%2,%3}, [%4];"
                 : "=r"(r[0]), "=r"(r[1]), "=r"(r[2]), "=r"(r[3]) : "r"(addr));
}
__device__ __forceinline__ void ldsm_x2(uint32_t* r, uint32_t addr) {
    asm volatile("ldmatrix.sync.aligned.m8n8.x2.shared.b16 {%0,%1}, [%2];"
                 : "=r"(r[0]), "=r"(r[1]) : "r"(addr));
}
__device__ __forceinline__ void mma_16816(float* d, const uint32_t* a, const uint32_t* b) {
    asm volatile(
        "mma.sync.aligned.m16n8k16.row.col.f32.bf16.bf16.f32 "
        "{%0,%1,%2,%3}, {%4,%5,%6,%7}, {%8,%9}, {%0,%1,%2,%3};\n"
        : "+f"(d[0]), "+f"(d[1]), "+f"(d[2]), "+f"(d[3])
        : "r"(a[0]), "r"(a[1]), "r"(a[2]), "r"(a[3]), "r"(b[0]), "r"(b[1]));
}
__device__ __forceinline__ float sigf(float x) {
    return __fdividef(1.f, 1.f + __expf(-x));
}
__device__ __forceinline__ float tanhf_(float x) {
    return 1.f - __fdividef(2.f, 1.f + __expf(2.f * x));
}

// ---------------------------------------------------------------------------
// Conversion kernels
// ---------------------------------------------------------------------------
__global__ void conv_split(const float* __restrict__ in,
                           bf16* __restrict__ hi, bf16* __restrict__ lo, int n4)
{
    int i = blockIdx.x * blockDim.x + threadIdx.x;
    if (i >= n4) return;
    float4 v = ((const float4*)in)[i];
    union { bf16 b[4]; uint2 u; } H, L;
    H.b[0] = __float2bfloat16_rn(v.x);
    H.b[1] = __float2bfloat16_rn(v.y);
    H.b[2] = __float2bfloat16_rn(v.z);
    H.b[3] = __float2bfloat16_rn(v.w);
    L.b[0] = __float2bfloat16_rn(v.x - __bfloat162float(H.b[0]));
    L.b[1] = __float2bfloat16_rn(v.y - __bfloat162float(H.b[1]));
    L.b[2] = __float2bfloat16_rn(v.z - __bfloat162float(H.b[2]));
    L.b[3] = __float2bfloat16_rn(v.w - __bfloat162float(H.b[3]));
    ((uint2*)hi)[i] = H.u;
    ((uint2*)lo)[i] = L.u;
}

// Transpose + split + gate-pack: out row P = 4u+g <- input col n = g*H + u.
// M is [K, 4H]. (H=Hdim of this layer; for the recurrence U: K = H.)
__global__ void conv_w_packed(const float* __restrict__ M,
                              bf16* __restrict__ hi, bf16* __restrict__ lo,
                              int K, int Hdim)
{
    int idx = blockIdx.x * blockDim.x + threadIdx.x;
    int N = 4 * Hdim;
    if (idx >= N * K) return;
    int P = idx / K, k = idx - P * K;
    int n = (P & 3) * Hdim + (P >> 2);
    float v = M[(size_t)k * N + n];
    bf16 h = __float2bfloat16_rn(v);
    hi[idx] = h;
    lo[idx] = __float2bfloat16_rn(v - __bfloat162float(h));
}

// Permute bias into packed order
__global__ void conv_bias(const float* __restrict__ b, float* __restrict__ bp, int Hdim)
{
    int P = blockIdx.x * blockDim.x + threadIdx.x;
    if (P >= 4 * Hdim) return;
    bp[P] = b[(P & 3) * Hdim + (P >> 2)];
}

// ---------------------------------------------------------------------------
// mma.sync GEMM (proven): C[M,N] = (Ahi+Alo)@(Bhi+Blo)^T + bias
// B rows are packed-order; output C inherits packed column order.
// ---------------------------------------------------------------------------
#define TSTRIDE 72
#define GEMM_SMEM (4 * 128 * TSTRIDE * 2)

__global__ __launch_bounds__(256)
void mma_gemm(const bf16* __restrict__ Ahi, const bf16* __restrict__ Alo,
              const bf16* __restrict__ Bhi, const bf16* __restrict__ Blo,
              const float* __restrict__ bias, float* __restrict__ C, int K, int N)
{
    extern __shared__ bf16 sm[];
    bf16* sAhi = sm;
    bf16* sAlo = sm + 128 * TSTRIDE;
    bf16* sBhi = sm + 2 * 128 * TSTRIDE;
    bf16* sBlo = sm + 3 * 128 * TSTRIDE;
    const uint32_t uAhi = smem_u32(sAhi), uAlo = smem_u32(sAlo);
    const uint32_t uBhi = smem_u32(sBhi), uBlo = smem_u32(sBlo);

    const int tid = threadIdx.x;
    const int wid = tid >> 5, lane = tid & 31;
    const int warp_m = wid & 1, warp_n = wid >> 1;
    const int bm = blockIdx.y * 128, bn = blockIdx.x * 128;

    float acc[4][4][4];
#pragma unroll
    for (int mi = 0; mi < 4; mi++)
#pragma unroll
        for (int ni = 0; ni < 4; ni++)
#pragma unroll
            for (int f = 0; f < 4; f++) acc[mi][ni][f] = 0.f;

    const int r8  = lane & 7;
    const int grp = lane >> 3;
    const int aRowOff = ((grp & 1) ? 8 : 0) + r8;
    const int aColOff = (grp & 2) ? 8 : 0;
    const int bSel = grp & 1;

    const int nchunk = K >> 6;
    for (int c = 0; c < nchunk; c++) {
        const int k0g = c << 6;
#pragma unroll
        for (int i = 0; i < 4; i++) {
            int idx = tid + i * 256;
            int row = idx >> 3, seg = idx & 7;
            size_t ga = (size_t)(bm + row) * K + k0g + seg * 8;
            size_t gb = (size_t)(bn + row) * K + k0g + seg * 8;
            int so = row * TSTRIDE + seg * 8;
            *(uint4*)(sAhi + so) = *(const uint4*)&Ahi[ga];
            *(uint4*)(sAlo + so) = *(const uint4*)&Alo[ga];
            *(uint4*)(sBhi + so) = *(const uint4*)&Bhi[gb];
            *(uint4*)(sBlo + so) = *(const uint4*)&Blo[gb];
        }
        __syncthreads();

#pragma unroll
        for (int ks = 0; ks < 4; ks++) {
            const int k0 = ks * 16;
            uint32_t aHi[4][4], aLo[4][4], bHi[4][2], bLo[4][2];
#pragma unroll
            for (int mi = 0; mi < 4; mi++) {
                int row = warp_m * 64 + mi * 16 + aRowOff;
                uint32_t off = (uint32_t)(row * TSTRIDE + k0 + aColOff) * 2;
                ldsm_x4(aHi[mi], uAhi + off);
                ldsm_x4(aLo[mi], uAlo + off);
            }
#pragma unroll
            for (int ni = 0; ni < 4; ni++) {
                int row = warp_n * 32 + ni * 8 + r8;
                uint32_t off = (uint32_t)(row * TSTRIDE + k0 + bSel * 8) * 2;
                ldsm_x2(bHi[ni], uBhi + off);
                ldsm_x2(bLo[ni], uBlo + off);
            }
#pragma unroll
            for (int mi = 0; mi < 4; mi++)
#pragma unroll
                for (int ni = 0; ni < 4; ni++) {
                    mma_16816(acc[mi][ni], aHi[mi], bHi[ni]);
                    mma_16816(acc[mi][ni], aHi[mi], bLo[ni]);
                    mma_16816(acc[mi][ni], aLo[mi], bHi[ni]);
                }
        }
        __syncthreads();
    }

    const int tg = lane >> 2, tp = lane & 3;
#pragma unroll
    for (int mi = 0; mi < 4; mi++) {
#pragma unroll
        for (int ni = 0; ni < 4; ni++) {
            int col = bn + warp_n * 32 + ni * 8 + tp * 2;
            int row0 = bm + warp_m * 64 + mi * 16 + tg;
            float2 o0, o1;
            o0.x = acc[mi][ni][0] + bias[col];
            o0.y = acc[mi][ni][1] + bias[col + 1];
            o1.x = acc[mi][ni][2] + bias[col];
            o1.y = acc[mi][ni][3] + bias[col + 1];
            *(float2*)&C[(size_t)row0 * N + col] = o0;
            *(float2*)&C[(size_t)(row0 + 8) * N + col] = o1;
        }
    }
}

// ---------------------------------------------------------------------------
// Per-batch-block grid barrier: 16 CTAs per group, padded slots.
// Generation is re-read atomically at entry so the arrive/readiness ordering
// never depends on a stale volatile load.
// ---------------------------------------------------------------------------
__device__ __forceinline__ void group_barrier(int bb) {
    __syncthreads();
    if (threadIdx.x == 0) {
        __threadfence();
        unsigned int* cnt = &g_bcnt[bb * 32];
        unsigned int* gen = &g_bgen[bb * 32];
        unsigned int g = atomicAdd(gen, 0u);           // fresh read
        unsigned int arr = atomicAdd(cnt, 1u);
        if (arr == 15u) {
            *cnt = 0u;
            __threadfence();
            atomicAdd(gen, 1u);
        } else {
            while (*(volatile unsigned int*)gen == g) {
                __nanosleep(32);
            }
        }
        __threadfence();
    }
    __syncthreads();
}

// ---------------------------------------------------------------------------
// Tensor-core LSTM recurrence (persistent, 128 CTAs, 256 threads).
// Packed columns P = 4u+g everywhere (xW, U^T). 8 bb x 16 cb CTAs.
// xW prefetched into regs before the barrier; h staged via smem for
// coalesced 32B-row global stores.
// ---------------------------------------------------------------------------
template<int H>
__global__ __launch_bounds__(256, 1)
void lstm_mma(const float* __restrict__ xW,
              const bf16* __restrict__ Uthi, const bf16* __restrict__ Utlo,
              bf16* __restrict__ Hhi, bf16* __restrict__ Hlo)
{
    constexpr int K    = H;
    constexpr int KS   = K / 16;
    constexpr int UPC  = H / 16;       // units per CTA
    constexpr int PC   = 4 * UPC;      // packed cols per CTA
    constexpr int WN   = PC / 4;       // warp n-tile
    constexpr int NI   = WN / 8;
    constexpr int KS2  = K + 8;
    constexpr int FOURH = 4 * H;
    constexpr int U4R  = K / 8;
    constexpr int STW  = UPC / 2;      // uint32 per staged row

    extern __shared__ bf16 dyn[];
    bf16* sUhi = dyn;
    bf16* sUlo = dyn + PC * KS2;
    bf16* sHhi = dyn + 2 * PC * KS2;
    bf16* sHlo = dyn + 2 * PC * KS2 + 32 * KS2;
    bf16* sStHi = dyn + 2 * PC * KS2 + 64 * KS2;
    bf16* sStLo = sStHi + 32 * UPC;
    const uint32_t uUhi = smem_u32(sUhi), uUlo = smem_u32(sUlo);
    const uint32_t uHhi = smem_u32(sHhi), uHlo = smem_u32(sHlo);

    const int tid = threadIdx.x;
    const int wid = tid >> 5, lane = tid & 31;
    const int wm = wid & 1, wn = wid >> 1;
    const int cb = blockIdx.x & 15;
    const int bb = blockIdx.x >> 4;
    const int b0 = bb * 32;

    const int r8  = lane & 7;
    const int grp = lane >> 3;
    const int aRowOff = ((grp & 1) ? 8 : 0) + r8;
    const int aColOff = (grp & 2) ? 8 : 0;
    const int bSel = grp & 1;
    const int tg = lane >> 2, tp = lane & 3;
    const bool evenp = (tp & 1) == 0;

    // Persistent U^T slice: packed rows cb*PC .. cb*PC+PC-1 (contiguous)
    for (int idx = tid; idx < PC * U4R; idx += 256) {
        int p = idx / U4R, q = idx - p * U4R;
        size_t gsrc = (size_t)(cb * PC + p) * K + q * 8;
        *(uint4*)(sUhi + p * KS2 + q * 8) = *(const uint4*)&Uthi[gsrc];
        *(uint4*)(sUlo + p * KS2 + q * 8) = *(const uint4*)&Utlo[gsrc];
    }
    __syncthreads();

    // Hoist B-hi fragments (step-invariant)
    uint32_t bHi[KS][NI][2];
#pragma unroll
    for (int ks = 0; ks < KS; ks++)
#pragma unroll
        for (int ni = 0; ni < NI; ni++) {
            uint32_t off = (uint32_t)((wn * WN + ni * 8 + r8) * KS2 + ks * 16 + bSel * 8) * 2;
            ldsm_x2(bHi[ks][ni], uUhi + off);
        }

    const int rA = b0 + wm * 16 + tg;      // batch rows rA, rA+8
    const int colBase = cb * PC + wn * WN; // packed global col base for this warp
    int colg[NI];
#pragma unroll
    for (int ni = 0; ni < NI; ni++) colg[ni] = colBase + ni * 8 + 2 * tp;
    int uLoc[NI];
#pragma unroll
    for (int ni = 0; ni < NI; ni++) uLoc[ni] = (wn * WN + ni * 8 + 2 * tp) >> 2;

    float cst[NI][2];
#pragma unroll
    for (int ni = 0; ni < NI; ni++) { cst[ni][0] = 0.f; cst[ni][1] = 0.f; }

    const size_t xw0 = (size_t)rA * TLEN * FOURH;
    const size_t xw1 = (size_t)(rA + 8) * TLEN * FOURH;

    // Prefetch xW for t=0
    float nxt[NI][4];
#pragma unroll
    for (int ni = 0; ni < NI; ni++) {
        float2 a = *(const float2*)&xW[xw0 + colg[ni]];
        float2 b = *(const float2*)&xW[xw1 + colg[ni]];
        nxt[ni][0] = a.x; nxt[ni][1] = a.y; nxt[ni][2] = b.x; nxt[ni][3] = b.y;
    }

    for (int t = 0; t < TLEN; t++) {
        float acc[NI][4];
#pragma unroll
        for (int ni = 0; ni < NI; ni++) {
            acc[ni][0] = nxt[ni][0]; acc[ni][1] = nxt[ni][1];
            acc[ni][2] = nxt[ni][2]; acc[ni][3] = nxt[ni][3];
        }

        if (t > 0) {
            // Stage h(t-1) [32 x K] hi/lo into smem
            for (int idx = tid; idx < 32 * U4R; idx += 256) {
                int r = idx / U4R, q = idx - r * U4R;
                size_t g = ((size_t)(b0 + r) * TLEN + (t - 1)) * H + q * 8;
                *(uint4*)(sHhi + r * KS2 + q * 8) = *(const uint4*)&Hhi[g];
                *(uint4*)(sHlo + r * KS2 + q * 8) = *(const uint4*)&Hlo[g];
            }
            __syncthreads();

#pragma unroll
            for (int ks = 0; ks < KS; ks++) {
                uint32_t ahi[4], alo[4];
                uint32_t aoff = (uint32_t)((wm * 16 + aRowOff) * KS2 + ks * 16 + aColOff) * 2;
                ldsm_x4(ahi, uHhi + aoff);
                ldsm_x4(alo, uHlo + aoff);
#pragma unroll
                for (int ni = 0; ni < NI; ni++) {
                    uint32_t blo[2];
                    uint32_t boff = (uint32_t)((wn * WN + ni * 8 + r8) * KS2 + ks * 16 + bSel * 8) * 2;
                    ldsm_x2(blo, uUlo + boff);
                    mma_16816(acc[ni], ahi, bHi[ks][ni]);
                    mma_16816(acc[ni], ahi, blo);
                    mma_16816(acc[ni], alo, bHi[ks][ni]);
                }
            }
        }

        // Gates (even tp: i,f | odd tp: g,o of the same unit); write h to stage
#pragma unroll
        for (int ni = 0; ni < NI; ni++) {
            float v0, v1, v2, v3;
            if (evenp) {
                v0 = sigf(acc[ni][0]); v1 = sigf(acc[ni][1]);
                v2 = sigf(acc[ni][2]); v3 = sigf(acc[ni][3]);
            } else {
                v0 = tanhf_(acc[ni][0]); v1 = sigf(acc[ni][1]);
                v2 = tanhf_(acc[ni][2]); v3 = sigf(acc[ni][3]);
            }
            float p0 = __shfl_xor_sync(0xffffffffu, v0, 1);
            float p1 = __shfl_xor_sync(0xffffffffu, v1, 1);
            float p2 = __shfl_xor_sync(0xffffffffu, v2, 1);
            float p3 = __shfl_xor_sync(0xffffffffu, v3, 1);
            float i0 = evenp ? v0 : p0, f0 = evenp ? v1 : p1;
            float g0 = evenp ? p0 : v0, o0 = evenp ? p1 : v1;
            float i1 = evenp ? v2 : p2, f1 = evenp ? v3 : p3;
            float g1 = evenp ? p2 : v2, o1 = evenp ? p3 : v3;

            float c0 = fmaf(f0, cst[ni][0], i0 * g0);
            float c1 = fmaf(f1, cst[ni][1], i1 * g1);
            cst[ni][0] = c0;
            cst[ni][1] = c1;
            float h0 = o0 * tanhf_(c0);
            float h1 = o1 * tanhf_(c1);

            if (evenp) {
                int r0 = wm * 16 + tg, r1 = r0 + 8;
                bf16 h0h = __float2bfloat16_rn(h0);
                bf16 h1h = __float2bfloat16_rn(h1);
                sStHi[r0 * UPC + uLoc[ni]] = h0h;
                sStLo[r0 * UPC + uLoc[ni]] = __float2bfloat16_rn(h0 - __bfloat162float(h0h));
                sStHi[r1 * UPC + uLoc[ni]] = h1h;
                sStLo[r1 * UPC + uLoc[ni]] = __float2bfloat16_rn(h1 - __bfloat162float(h1h));
            }
        }

        // Prefetch next step's xW (hidden under store + barrier)
        if (t + 1 < TLEN) {
            size_t o = (size_t)(t + 1) * FOURH;
#pragma unroll
            for (int ni = 0; ni < NI; ni++) {
                float2 a = *(const float2*)&xW[xw0 + o + colg[ni]];
                float2 b = *(const float2*)&xW[xw1 + o + colg[ni]];
                nxt[ni][0] = a.x; nxt[ni][1] = a.y; nxt[ni][2] = b.x; nxt[ni][3] = b.y;
            }
        }

        __syncthreads();
        // Coalesced h store: 32 rows x UPC units (hi & lo)
        for (int idx = tid; idx < 32 * STW; idx += 256) {
            int r = idx / STW, q = idx - r * STW;
            size_t gaddr = ((size_t)(b0 + r) * TLEN + t) * H + cb * UPC + q * 2;
            *(uint32_t*)&Hhi[gaddr] = ((const uint32_t*)sStHi)[r * STW + q];
            *(uint32_t*)&Hlo[gaddr] = ((const uint32_t*)sStLo)[r * STW + q];
        }

        if (t < TLEN - 1) group_barrier(bb);
    }
}

// ---------------------------------------------------------------------------
// Final dense: out[b,d] = (hi+lo)[b,T-1,:128] @ Wd + bd
// ---------------------------------------------------------------------------
__global__ void dense_kernel(const bf16* __restrict__ Hhi, const bf16* __restrict__ Hlo,
                             const float* __restrict__ Wd, const float* __restrict__ bd,
                             float* __restrict__ out)
{
    int b = blockIdx.x;
    int d = threadIdx.x;
    size_t base = ((size_t)b * TLEN + (TLEN - 1)) * 128;
    float acc = 0.f;
#pragma unroll 4
    for (int k = 0; k < 128; k++) {
        float h = __bfloat162float(Hhi[base + k]) + __bfloat162float(Hlo[base + k]);
        acc = fmaf(h, Wd[k * 64 + d], acc);
    }
    out[b * 64 + d] = acc + bd[d];
}

// ---------------------------------------------------------------------------
// Launch sequence
// ---------------------------------------------------------------------------
extern "C" void kernel_launch(void* const* d_in, const int* in_sizes, int n_in,
                              void* d_out, int out_size)
{
    (void)in_sizes; (void)n_in; (void)out_size;
    const float* x  = (const float*)d_in[0];
    const float* W0 = (const float*)d_in[1];
    const float* U0 = (const float*)d_in[2];
    const float* b0 = (const float*)d_in[3];
    const float* W1 = (const float*)d_in[4];
    const float* U1 = (const float*)d_in[5];
    const float* b1 = (const float*)d_in[6];
    const float* W2 = (const float*)d_in[7];
    const float* U2 = (const float*)d_in[8];
    const float* b2 = (const float*)d_in[9];
    const float* Wd = (const float*)d_in[10];
    const float* bd = (const float*)d_in[11];
    float* out = (float*)d_out;

    void* p;
    cudaGetSymbolAddress(&p, g_xW);   float* xw = (float*)p;
    cudaGetSymbolAddress(&p, g_Ahi);  bf16* ahi = (bf16*)p;
    cudaGetSymbolAddress(&p, g_Alo);  bf16* alo = (bf16*)p;
    cudaGetSymbolAddress(&p, g_Wthi); bf16* whi = (bf16*)p;
    cudaGetSymbolAddress(&p, g_Wtlo); bf16* wlo = (bf16*)p;
    cudaGetSymbolAddress(&p, g_Uthi); bf16* uhi = (bf16*)p;
    cudaGetSymbolAddress(&p, g_Utlo); bf16* ulo = (bf16*)p;
    cudaGetSymbolAddress(&p, g_bias); float* bp = (float*)p;

    cudaFuncSetAttribute(mma_gemm, cudaFuncAttributeMaxDynamicSharedMemorySize, GEMM_SMEM);
    // smem: U(2*PC*KS2) + H(2*32*KS2) + stage(2*32*UPC), elems*2 bytes
    const int LS256 = (2 * 64 * 264 + 64 * 264 + 2 * 32 * 16) * 2;
    const int LS128 = (2 * 32 * 136 + 64 * 136 + 2 * 32 * 8) * 2;
    cudaFuncSetAttribute(lstm_mma<256>, cudaFuncAttributeMaxDynamicSharedMemorySize, LS256);
    cudaFuncSetAttribute(lstm_mma<128>, cudaFuncAttributeMaxDynamicSharedMemorySize, LS128);

    // Packed weight transposes + splits
    conv_w_packed<<<(1024 * 64  + 255) / 256, 256>>>(W0, whi + WOFF0, wlo + WOFF0, 64,  256);
    conv_w_packed<<<(1024 * 256 + 255) / 256, 256>>>(W1, whi + WOFF1, wlo + WOFF1, 256, 256);
    conv_w_packed<<<(512  * 256 + 255) / 256, 256>>>(W2, whi + WOFF2, wlo + WOFF2, 256, 128);
    conv_w_packed<<<(1024 * 256 + 255) / 256, 256>>>(U0, uhi + UOFF0, ulo + UOFF0, 256, 256);
    conv_w_packed<<<(1024 * 256 + 255) / 256, 256>>>(U1, uhi + UOFF1, ulo + UOFF1, 256, 256);
    conv_w_packed<<<(512  * 128 + 255) / 256, 256>>>(U2, uhi + UOFF2, ulo + UOFF2, 128, 128);

    const int M = MTOT;

    // Layer 0
    conv_split<<<(M * 64 / 4 + 255) / 256, 256>>>(x, ahi, alo, M * 64 / 4);
    conv_bias<<<4, 256>>>(b0, bp, 256);
    mma_gemm<<<dim3(8, M / 128), 256, GEMM_SMEM>>>(ahi, alo, whi + WOFF0, wlo + WOFF0,
                                                   bp, xw, 64, 1024);
    lstm_mma<256><<<128, 256, LS256>>>(xw, uhi + UOFF0, ulo + UOFF0, ahi, alo);

    // Layer 1
    conv_bias<<<4, 256>>>(b1, bp, 256);
    mma_gemm<<<dim3(8, M / 128), 256, GEMM_SMEM>>>(ahi, alo, whi + WOFF1, wlo + WOFF1,
                                                   bp, xw, 256, 1024);
    lstm_mma<256><<<128, 256, LS256>>>(xw, uhi + UOFF1, ulo + UOFF1, ahi, alo);

    // Layer 2
    conv_bias<<<2, 256>>>(b2, bp, 128);
    mma_gemm<<<dim3(4, M / 128), 256, GEMM_SMEM>>>(ahi, alo, whi + WOFF2, wlo + WOFF2,
                                                   bp, xw, 256, 512);
    lstm_mma<128><<<128, 256, LS128>>>(xw, uhi + UOFF2, ulo + UOFF2, ahi, alo);

    // Dense head
    dense_kernel<<<BSZ, 64>>>(ahi, alo, Wd, bd, out);
}

// round 9
// speedup vs baseline: 3.6862x; 1.4615x over previous
#include <cuda_runtime.h>
#include <cuda_bf16.h>
#include <cstdint>
#include <cstddef>

#define BSZ  256
#define TLEN 512
#define DIN  64
#define MTOT (BSZ * TLEN)

typedef __nv_bfloat16 bf16;

// ---------------------------------------------------------------------------
// Device-global scratch
// ---------------------------------------------------------------------------
__device__ float g_xW[MTOT * 1024];            // xW0 = x@W0 + b0, packed cols
__device__ bf16  g_Ahi[MTOT * 64];             // x split (layer-0 GEMM A)
__device__ bf16  g_Alo[MTOT * 64];
__device__ bf16  g_Wthi[458752];               // W^T packed (3 layers), hi
__device__ bf16  g_Wtlo[458752];
__device__ bf16  g_Uthi[589824];               // U^T packed (3 layers)
__device__ bf16  g_Utlo[589824];
__device__ float g_bias[1024];                 // packed b0 (for xW GEMM)
__device__ float g_biasP[1536];                // packed b1 [0:1024), b2 [1024:1536)
__device__ bf16  g_H0hi[MTOT * 256];           // h sequences (bf16 split)
__device__ bf16  g_H0lo[MTOT * 256];
__device__ bf16  g_H1hi[MTOT * 256];
__device__ bf16  g_H1lo[MTOT * 256];
__device__ bf16  g_H2hi[MTOT * 128];
__device__ bf16  g_H2lo[MTOT * 128];
__device__ unsigned int g_prog[8];             // [0..3]=L0 bb, [4..7]=L1 bb
__device__ unsigned int g_bcnt[12 * 32];       // 12 group-barrier slots, padded
__device__ unsigned int g_bgen[12 * 32];

#define WOFF0 0
#define WOFF1 (1024 * 64)
#define WOFF2 (1024 * 64 + 1024 * 256)
#define UOFF0 0
#define UOFF1 (1024 * 256)
#define UOFF2 (2 * 1024 * 256)

// ---------------------------------------------------------------------------
// sm_100-safe helpers (ldmatrix + mma.sync; no tcgen05)
// ---------------------------------------------------------------------------
__device__ __forceinline__ uint32_t smem_u32(const void* p) {
    uint32_t a;
    asm("{ .reg .u64 t; cvta.to.shared.u64 t, %1; cvt.u32.u64 %0, t; }"
        : "=r"(a) : "l"(p));
    return a;
}
__device__ __forceinline__ void ldsm_x4(uint32_t* r, uint32_t addr) {
    asm volatile("ldmatrix.sync.aligned.m8n8.x4.shared.b16 {%0,%1,%2,%3}, [%4];"
                 : "=r"(r[0]), "=r"(r[1]), "=r"(r[2]), "=r"(r[3]) : "r"(addr));
}
__device__ __forceinline__ void ldsm_x2(uint32_t* r, uint32_t addr) {
    asm volatile("ldmatrix.sync.aligned.m8n8.x2.shared.b16 {%0,%1}, [%2];"
                 : "=r"(r[0]), "=r"(r[1]) : "r"(addr));
}
__device__ __forceinline__ void mma_16816(float* d, const uint32_t* a, const uint32_t* b) {
    asm volatile(
        "mma.sync.aligned.m16n8k16.row.col.f32.bf16.bf16.f32 "
        "{%0,%1,%2,%3}, {%4,%5,%6,%7}, {%8,%9}, {%0,%1,%2,%3};\n"
        : "+f"(d[0]), "+f"(d[1]), "+f"(d[2]), "+f"(d[3])
        : "r"(a[0]), "r"(a[1]), "r"(a[2]), "r"(a[3]), "r"(b[0]), "r"(b[1]));
}
__device__ __forceinline__ float sigf(float x) {
    return __fdividef(1.f, 1.f + __expf(-x));
}
__device__ __forceinline__ float tanhf_(float x) {
    return 1.f - __fdividef(2.f, 1.f + __expf(2.f * x));
}

// ---------------------------------------------------------------------------
// Bounded sync primitives (a bug degrades to wrong output, never a hang)
// ---------------------------------------------------------------------------
__device__ __forceinline__ void wait_prog_ge(int slot, unsigned int tgt) {
    if (threadIdx.x == 0) {
        for (int it = 0; it < (1 << 18); it++) {
            if (*(volatile unsigned int*)&g_prog[slot] >= tgt) break;
            __nanosleep(32);
        }
        __threadfence();
    }
    __syncthreads();
}

__device__ __forceinline__ void group_barrier_n(int slot, unsigned int n) {
    __syncthreads();
    if (threadIdx.x == 0) {
        __threadfence();
        unsigned int* cnt = &g_bcnt[slot * 32];
        unsigned int* gen = &g_bgen[slot * 32];
        unsigned int g = atomicAdd(gen, 0u);
        unsigned int arr = atomicAdd(cnt, 1u);
        if (arr == n - 1u) {
            *cnt = 0u;
            __threadfence();
            atomicAdd(gen, 1u);
        } else {
            for (int it = 0; it < (1 << 18); it++) {
                if (*(volatile unsigned int*)gen != g) break;
                __nanosleep(32);
            }
        }
        __threadfence();
    }
    __syncthreads();
}

__global__ void reset_sync() {
    int i = threadIdx.x;
    if (i < 8) g_prog[i] = 0;
    for (int j = i; j < 12 * 32; j += 256) { g_bcnt[j] = 0; g_bgen[j] = 0; }
}

// ---------------------------------------------------------------------------
// Conversion kernels
// ---------------------------------------------------------------------------
__global__ void conv_split(const float* __restrict__ in,
                           bf16* __restrict__ hi, bf16* __restrict__ lo, int n4)
{
    int i = blockIdx.x * blockDim.x + threadIdx.x;
    if (i >= n4) return;
    float4 v = ((const float4*)in)[i];
    union { bf16 b[4]; uint2 u; } H, L;
    H.b[0] = __float2bfloat16_rn(v.x);
    H.b[1] = __float2bfloat16_rn(v.y);
    H.b[2] = __float2bfloat16_rn(v.z);
    H.b[3] = __float2bfloat16_rn(v.w);
    L.b[0] = __float2bfloat16_rn(v.x - __bfloat162float(H.b[0]));
    L.b[1] = __float2bfloat16_rn(v.y - __bfloat162float(H.b[1]));
    L.b[2] = __float2bfloat16_rn(v.z - __bfloat162float(H.b[2]));
    L.b[3] = __float2bfloat16_rn(v.w - __bfloat162float(H.b[3]));
    ((uint2*)hi)[i] = H.u;
    ((uint2*)lo)[i] = L.u;
}

// Transpose + split + gate-pack: out row P = 4u+g <- input col n = g*H + u.
__global__ void conv_w_packed(const float* __restrict__ M,
                              bf16* __restrict__ hi, bf16* __restrict__ lo,
                              int K, int Hdim)
{
    int idx = blockIdx.x * blockDim.x + threadIdx.x;
    int N = 4 * Hdim;
    if (idx >= N * K) return;
    int P = idx / K, k = idx - P * K;
    int n = (P & 3) * Hdim + (P >> 2);
    float v = M[(size_t)k * N + n];
    bf16 h = __float2bfloat16_rn(v);
    hi[idx] = h;
    lo[idx] = __float2bfloat16_rn(v - __bfloat162float(h));
}

__global__ void conv_bias(const float* __restrict__ b, float* __restrict__ bp, int Hdim)
{
    int P = blockIdx.x * blockDim.x + threadIdx.x;
    if (P >= 4 * Hdim) return;
    bp[P] = b[(P & 3) * Hdim + (P >> 2)];
}

// ---------------------------------------------------------------------------
// mma.sync GEMM (proven): used only for layer-0 xW precompute (K=64)
// ---------------------------------------------------------------------------
#define TSTRIDE 72
#define GEMM_SMEM (4 * 128 * TSTRIDE * 2)

__global__ __launch_bounds__(256)
void mma_gemm(const bf16* __restrict__ Ahi, const bf16* __restrict__ Alo,
              const bf16* __restrict__ Bhi, const bf16* __restrict__ Blo,
              const float* __restrict__ bias, float* __restrict__ C, int K, int N)
{
    extern __shared__ bf16 sm[];
    bf16* sAhi = sm;
    bf16* sAlo = sm + 128 * TSTRIDE;
    bf16* sBhi = sm + 2 * 128 * TSTRIDE;
    bf16* sBlo = sm + 3 * 128 * TSTRIDE;
    const uint32_t uAhi = smem_u32(sAhi), uAlo = smem_u32(sAlo);
    const uint32_t uBhi = smem_u32(sBhi), uBlo = smem_u32(sBlo);

    const int tid = threadIdx.x;
    const int wid = tid >> 5, lane = tid & 31;
    const int warp_m = wid & 1, warp_n = wid >> 1;
    const int bm = blockIdx.y * 128, bn = blockIdx.x * 128;

    float acc[4][4][4];
#pragma unroll
    for (int mi = 0; mi < 4; mi++)
#pragma unroll
        for (int ni = 0; ni < 4; ni++)
#pragma unroll
            for (int f = 0; f < 4; f++) acc[mi][ni][f] = 0.f;

    const int r8  = lane & 7;
    const int grp = lane >> 3;
    const int aRowOff = ((grp & 1) ? 8 : 0) + r8;
    const int aColOff = (grp & 2) ? 8 : 0;
    const int bSel = grp & 1;

    const int nchunk = K >> 6;
    for (int c = 0; c < nchunk; c++) {
        const int k0g = c << 6;
#pragma unroll
        for (int i = 0; i < 4; i++) {
            int idx = tid + i * 256;
            int row = idx >> 3, seg = idx & 7;
            size_t ga = (size_t)(bm + row) * K + k0g + seg * 8;
            size_t gb = (size_t)(bn + row) * K + k0g + seg * 8;
            int so = row * TSTRIDE + seg * 8;
            *(uint4*)(sAhi + so) = *(const uint4*)&Ahi[ga];
            *(uint4*)(sAlo + so) = *(const uint4*)&Alo[ga];
            *(uint4*)(sBhi + so) = *(const uint4*)&Bhi[gb];
            *(uint4*)(sBlo + so) = *(const uint4*)&Blo[gb];
        }
        __syncthreads();

#pragma unroll
        for (int ks = 0; ks < 4; ks++) {
            const int k0 = ks * 16;
            uint32_t aHi[4][4], aLo[4][4], bHi[4][2], bLo[4][2];
#pragma unroll
            for (int mi = 0; mi < 4; mi++) {
                int row = warp_m * 64 + mi * 16 + aRowOff;
                uint32_t off = (uint32_t)(row * TSTRIDE + k0 + aColOff) * 2;
                ldsm_x4(aHi[mi], uAhi + off);
                ldsm_x4(aLo[mi], uAlo + off);
            }
#pragma unroll
            for (int ni = 0; ni < 4; ni++) {
                int row = warp_n * 32 + ni * 8 + r8;
                uint32_t off = (uint32_t)(row * TSTRIDE + k0 + bSel * 8) * 2;
                ldsm_x2(bHi[ni], uBhi + off);
                ldsm_x2(bLo[ni], uBlo + off);
            }
#pragma unroll
            for (int mi = 0; mi < 4; mi++)
#pragma unroll
                for (int ni = 0; ni < 4; ni++) {
                    mma_16816(acc[mi][ni], aHi[mi], bHi[ni]);
                    mma_16816(acc[mi][ni], aHi[mi], bLo[ni]);
                    mma_16816(acc[mi][ni], aLo[mi], bHi[ni]);
                }
        }
        __syncthreads();
    }

    const int tg = lane >> 2, tp = lane & 3;
#pragma unroll
    for (int mi = 0; mi < 4; mi++) {
#pragma unroll
        for (int ni = 0; ni < 4; ni++) {
            int col = bn + warp_n * 32 + ni * 8 + tp * 2;
            int row0 = bm + warp_m * 64 + mi * 16 + tg;
            float2 o0, o1;
            o0.x = acc[mi][ni][0] + bias[col];
            o0.y = acc[mi][ni][1] + bias[col + 1];
            o1.x = acc[mi][ni][2] + bias[col];
            o1.y = acc[mi][ni][3] + bias[col + 1];
            *(float2*)&C[(size_t)row0 * N + col] = o0;
            *(float2*)&C[(size_t)(row0 + 8) * N + col] = o1;
        }
    }
}

// ---------------------------------------------------------------------------
// Fused wavefront LSTM: one persistent kernel, 3 layers pipelined over t.
// Per-layer groups of 64 batch rows; h exchanged via global + group barrier;
// cross-layer handoff via monotonic progress counters.
// Packed cols P = 4u+g everywhere; 3-term bf16 split everywhere.
// ---------------------------------------------------------------------------
template<int HDIM, int KIN, int UPCv, int GRPN>
__device__ void run_layer(int bb, int cb, int gslot, int pubslot, int waitslot,
    const bf16* __restrict__ Uthi, const bf16* __restrict__ Utlo,
    const bf16* __restrict__ Wthi, const bf16* __restrict__ Wtlo,
    const float* __restrict__ biasp, const float* __restrict__ xW,
    const bf16* __restrict__ Hin_hi, const bf16* __restrict__ Hin_lo,
    bf16* __restrict__ Hhi, bf16* __restrict__ Hlo)
{
    constexpr int K    = HDIM;
    constexpr int PC   = 4 * UPCv;
    constexpr int WN   = PC / 4;
    constexpr int NI   = WN / 8;
    constexpr int KSU  = K / 16;
    constexpr int KS2U = K + 8;
    constexpr int U4U  = K / 8;
    constexpr int KSW  = KIN / 16;
    constexpr int KS2W = KIN + 8;
    constexpr int U4W  = KIN / 8;
    constexpr int KS2M = (KS2W > KS2U) ? KS2W : KS2U;
    constexpr int STW  = UPCv / 2;

    extern __shared__ bf16 dyn[];
    bf16* sUhi  = dyn;                               // PC x KS2U
    bf16* sUlo  = sUhi + PC * KS2U;
    bf16* sWhi  = sUlo + PC * KS2U;                  // PC x KS2W (if KIN)
    bf16* sWlo  = sWhi + (KIN ? PC * KS2W : 0);
    bf16* sHs_hi = sWlo + (KIN ? PC * KS2W : 0);     // 64 x KS2M (A staging)
    bf16* sHs_lo = sHs_hi + 64 * KS2M;
    bf16* sSthi  = sHs_lo + 64 * KS2M;               // 64 x UPC stage-out
    bf16* sStlo  = sSthi + 64 * UPCv;
    const uint32_t uUhi = smem_u32(sUhi), uUlo = smem_u32(sUlo);
    const uint32_t uWhi = smem_u32(sWhi), uWlo = smem_u32(sWlo);
    const uint32_t uHhi = smem_u32(sHs_hi), uHlo = smem_u32(sHs_lo);

    const int tid = threadIdx.x;
    const int wid = tid >> 5, lane = tid & 31;
    const int wm = wid & 1, wn = wid >> 1;
    const int b0 = bb * 64;

    const int r8  = lane & 7;
    const int grp = lane >> 3;
    const int aRowOff = ((grp & 1) ? 8 : 0) + r8;
    const int aColOff = (grp & 2) ? 8 : 0;
    const int bSel = grp & 1;
    const int tg = lane >> 2, tp = lane & 3;
    const bool evenp = (tp & 1) == 0;

    // Persistent U^T slice (packed rows cb*PC ..)
    for (int idx = tid; idx < PC * U4U; idx += 256) {
        int p = idx / U4U, q = idx - p * U4U;
        size_t g = (size_t)(cb * PC + p) * K + q * 8;
        *(uint4*)(sUhi + p * KS2U + q * 8) = *(const uint4*)&Uthi[g];
        *(uint4*)(sUlo + p * KS2U + q * 8) = *(const uint4*)&Utlo[g];
    }
    if constexpr (KIN > 0) {
        for (int idx = tid; idx < PC * U4W; idx += 256) {
            int p = idx / U4W, q = idx - p * U4W;
            size_t g = (size_t)(cb * PC + p) * KIN + q * 8;
            *(uint4*)(sWhi + p * KS2W + q * 8) = *(const uint4*)&Wthi[g];
            *(uint4*)(sWlo + p * KS2W + q * 8) = *(const uint4*)&Wtlo[g];
        }
    }
    __syncthreads();

    int colg[NI], uLoc[NI];
#pragma unroll
    for (int ni = 0; ni < NI; ni++) {
        int pcl = wn * WN + ni * 8 + 2 * tp;
        colg[ni] = cb * PC + pcl;
        uLoc[ni] = pcl >> 2;
    }
    float bs[NI][2];
    if constexpr (KIN > 0) {
#pragma unroll
        for (int ni = 0; ni < NI; ni++) {
            bs[ni][0] = biasp[colg[ni]];
            bs[ni][1] = biasp[colg[ni] + 1];
        }
    }

    float cst[2][NI][2];
#pragma unroll
    for (int mi = 0; mi < 2; mi++)
#pragma unroll
        for (int ni = 0; ni < NI; ni++) { cst[mi][ni][0] = 0.f; cst[mi][ni][1] = 0.f; }

    float nxt[2][NI][4];
    if constexpr (KIN == 0) {
#pragma unroll
        for (int mi = 0; mi < 2; mi++) {
            size_t row = (size_t)(b0 + wm * 32 + mi * 16 + tg);
#pragma unroll
            for (int ni = 0; ni < NI; ni++) {
                float2 a = *(const float2*)&xW[(row * TLEN) * (4 * HDIM) + colg[ni]];
                float2 b = *(const float2*)&xW[((row + 8) * TLEN) * (4 * HDIM) + colg[ni]];
                nxt[mi][ni][0] = a.x; nxt[mi][ni][1] = a.y;
                nxt[mi][ni][2] = b.x; nxt[mi][ni][3] = b.y;
            }
        }
    }

    for (int t = 0; t < TLEN; t++) {
        if constexpr (KIN > 0) wait_prog_ge(waitslot, (unsigned)(t + 1));

        float acc[2][NI][4];
#pragma unroll
        for (int mi = 0; mi < 2; mi++)
#pragma unroll
            for (int ni = 0; ni < NI; ni++) {
                if constexpr (KIN == 0) {
                    acc[mi][ni][0] = nxt[mi][ni][0]; acc[mi][ni][1] = nxt[mi][ni][1];
                    acc[mi][ni][2] = nxt[mi][ni][2]; acc[mi][ni][3] = nxt[mi][ni][3];
                } else {
                    acc[mi][ni][0] = bs[ni][0]; acc[mi][ni][1] = bs[ni][1];
                    acc[mi][ni][2] = bs[ni][0]; acc[mi][ni][3] = bs[ni][1];
                }
            }

        if constexpr (KIN > 0) {
            // Input GEMM: stage h_in(t), then W-mma
            for (int idx = tid; idx < 64 * U4W; idx += 256) {
                int r = idx / U4W, q = idx - r * U4W;
                size_t g = ((size_t)(b0 + r) * TLEN + t) * KIN + q * 8;
                *(uint4*)(sHs_hi + r * KS2W + q * 8) = *(const uint4*)&Hin_hi[g];
                *(uint4*)(sHs_lo + r * KS2W + q * 8) = *(const uint4*)&Hin_lo[g];
            }
            __syncthreads();
#pragma unroll
            for (int ks = 0; ks < KSW; ks++) {
                uint32_t ahi[2][4], alo[2][4];
#pragma unroll
                for (int mi = 0; mi < 2; mi++) {
                    uint32_t aoff = (uint32_t)((wm * 32 + mi * 16 + aRowOff) * KS2W
                                               + ks * 16 + aColOff) * 2;
                    ldsm_x4(ahi[mi], uHhi + aoff);
                    ldsm_x4(alo[mi], uHlo + aoff);
                }
#pragma unroll
                for (int ni = 0; ni < NI; ni++) {
                    uint32_t bh[2], bl[2];
                    uint32_t boff = (uint32_t)((wn * WN + ni * 8 + r8) * KS2W
                                               + ks * 16 + bSel * 8) * 2;
                    ldsm_x2(bh, uWhi + boff);
                    ldsm_x2(bl, uWlo + boff);
#pragma unroll
                    for (int mi = 0; mi < 2; mi++) {
                        mma_16816(acc[mi][ni], ahi[mi], bh);
                        mma_16816(acc[mi][ni], ahi[mi], bl);
                        mma_16816(acc[mi][ni], alo[mi], bh);
                    }
                }
            }
            __syncthreads();
        }

        if (t > 0) {
            // Recurrent GEMM: stage own h(t-1), then U-mma
            for (int idx = tid; idx < 64 * U4U; idx += 256) {
                int r = idx / U4U, q = idx - r * U4U;
                size_t g = ((size_t)(b0 + r) * TLEN + (t - 1)) * HDIM + q * 8;
                *(uint4*)(sHs_hi + r * KS2U + q * 8) = *(const uint4*)&Hhi[g];
                *(uint4*)(sHs_lo + r * KS2U + q * 8) = *(const uint4*)&Hlo[g];
            }
            __syncthreads();
#pragma unroll
            for (int ks = 0; ks < KSU; ks++) {
                uint32_t ahi[2][4], alo[2][4];
#pragma unroll
                for (int mi = 0; mi < 2; mi++) {
                    uint32_t aoff = (uint32_t)((wm * 32 + mi * 16 + aRowOff) * KS2U
                                               + ks * 16 + aColOff) * 2;
                    ldsm_x4(ahi[mi], uHhi + aoff);
                    ldsm_x4(alo[mi], uHlo + aoff);
                }
#pragma unroll
                for (int ni = 0; ni < NI; ni++) {
                    uint32_t bh[2], bl[2];
                    uint32_t boff = (uint32_t)((wn * WN + ni * 8 + r8) * KS2U
                                               + ks * 16 + bSel * 8) * 2;
                    ldsm_x2(bh, uUhi + boff);
                    ldsm_x2(bl, uUlo + boff);
#pragma unroll
                    for (int mi = 0; mi < 2; mi++) {
                        mma_16816(acc[mi][ni], ahi[mi], bh);
                        mma_16816(acc[mi][ni], ahi[mi], bl);
                        mma_16816(acc[mi][ni], alo[mi], bh);
                    }
                }
            }
        }

        // Gates (even tp: i,f | odd tp: g,o of same unit); stage h out
#pragma unroll
        for (int mi = 0; mi < 2; mi++) {
#pragma unroll
            for (int ni = 0; ni < NI; ni++) {
                float v0, v1, v2, v3;
                if (evenp) {
                    v0 = sigf(acc[mi][ni][0]); v1 = sigf(acc[mi][ni][1]);
                    v2 = sigf(acc[mi][ni][2]); v3 = sigf(acc[mi][ni][3]);
                } else {
                    v0 = tanhf_(acc[mi][ni][0]); v1 = sigf(acc[mi][ni][1]);
                    v2 = tanhf_(acc[mi][ni][2]); v3 = sigf(acc[mi][ni][3]);
                }
                float p0 = __shfl_xor_sync(0xffffffffu, v0, 1);
                float p1 = __shfl_xor_sync(0xffffffffu, v1, 1);
                float p2 = __shfl_xor_sync(0xffffffffu, v2, 1);
                float p3 = __shfl_xor_sync(0xffffffffu, v3, 1);
                float i0 = evenp ? v0 : p0, f0 = evenp ? v1 : p1;
                float g0 = evenp ? p0 : v0, o0 = evenp ? p1 : v1;
                float i1 = evenp ? v2 : p2, f1 = evenp ? v3 : p3;
                float g1 = evenp ? p2 : v2, o1 = evenp ? p3 : v3;

                float c0 = fmaf(f0, cst[mi][ni][0], i0 * g0);
                float c1 = fmaf(f1, cst[mi][ni][1], i1 * g1);
                cst[mi][ni][0] = c0;
                cst[mi][ni][1] = c1;
                float h0 = o0 * tanhf_(c0);
                float h1 = o1 * tanhf_(c1);

                if (evenp) {
                    int r0 = wm * 32 + mi * 16 + tg, r1 = r0 + 8;
                    bf16 h0h = __float2bfloat16_rn(h0);
                    bf16 h1h = __float2bfloat16_rn(h1);
                    sSthi[r0 * UPCv + uLoc[ni]] = h0h;
                    sStlo[r0 * UPCv + uLoc[ni]] = __float2bfloat16_rn(h0 - __bfloat162float(h0h));
                    sSthi[r1 * UPCv + uLoc[ni]] = h1h;
                    sStlo[r1 * UPCv + uLoc[ni]] = __float2bfloat16_rn(h1 - __bfloat162float(h1h));
                }
            }
        }

        // L0: prefetch next xW (hidden under store + barrier)
        if constexpr (KIN == 0) {
            if (t + 1 < TLEN) {
#pragma unroll
                for (int mi = 0; mi < 2; mi++) {
                    size_t row = (size_t)(b0 + wm * 32 + mi * 16 + tg);
#pragma unroll
                    for (int ni = 0; ni < NI; ni++) {
                        float2 a = *(const float2*)&xW[(row * TLEN + t + 1) * (4 * HDIM) + colg[ni]];
                        float2 b = *(const float2*)&xW[((row + 8) * TLEN + t + 1) * (4 * HDIM) + colg[ni]];
                        nxt[mi][ni][0] = a.x; nxt[mi][ni][1] = a.y;
                        nxt[mi][ni][2] = b.x; nxt[mi][ni][3] = b.y;
                    }
                }
            }
        }

        __syncthreads();
        // Coalesced h store (hi & lo)
        for (int idx = tid; idx < 64 * STW; idx += 256) {
            int r = idx / STW, q = idx - r * STW;
            size_t g = ((size_t)(b0 + r) * TLEN + t) * HDIM + cb * UPCv + q * 2;
            *(uint32_t*)&Hhi[g] = ((const uint32_t*)sSthi)[r * STW + q];
            *(uint32_t*)&Hlo[g] = ((const uint32_t*)sStlo)[r * STW + q];
        }

        group_barrier_n(gslot, GRPN);
        if (pubslot >= 0 && cb == 0 && tid == 0)
            atomicExch(&g_prog[pubslot], (unsigned)(t + 1));
    }
}

__global__ __launch_bounds__(256, 1) void fused_lstm()
{
    int bx = blockIdx.x;
    if (bx < 32) {
        int bb = bx >> 3, cb = bx & 7;
        run_layer<256, 0, 32, 8>(bb, cb, bb, bb, -1,
            g_Uthi + UOFF0, g_Utlo + UOFF0, nullptr, nullptr,
            nullptr, g_xW, nullptr, nullptr, g_H0hi, g_H0lo);
    } else if (bx < 96) {
        int l = bx - 32;
        int bb = l >> 4, cb = l & 15;
        run_layer<256, 256, 16, 16>(bb, cb, 4 + bb, 4 + bb, bb,
            g_Uthi + UOFF1, g_Utlo + UOFF1, g_Wthi + WOFF1, g_Wtlo + WOFF1,
            g_biasP, nullptr, g_H0hi, g_H0lo, g_H1hi, g_H1lo);
    } else {
        int l = bx - 96;
        int bb = l >> 3, cb = l & 7;
        run_layer<128, 256, 16, 8>(bb, cb, 8 + bb, -1, 4 + bb,
            g_Uthi + UOFF2, g_Utlo + UOFF2, g_Wthi + WOFF2, g_Wtlo + WOFF2,
            g_biasP + 1024, nullptr, g_H1hi, g_H1lo, g_H2hi, g_H2lo);
    }
}

// ---------------------------------------------------------------------------
// Final dense: out[b,d] = (hi+lo)[b,T-1,:128] @ Wd + bd
// ---------------------------------------------------------------------------
__global__ void dense_kernel(const float* __restrict__ Wd, const float* __restrict__ bd,
                             float* __restrict__ out)
{
    int b = blockIdx.x;
    int d = threadIdx.x;
    size_t base = ((size_t)b * TLEN + (TLEN - 1)) * 128;
    float acc = 0.f;
#pragma unroll 4
    for (int k = 0; k < 128; k++) {
        float h = __bfloat162float(g_H2hi[base + k]) + __bfloat162float(g_H2lo[base + k]);
        acc = fmaf(h, Wd[k * 64 + d], acc);
    }
    out[b * 64 + d] = acc + bd[d];
}

// ---------------------------------------------------------------------------
// Launch sequence
// ---------------------------------------------------------------------------
// Fused smem (L0 is max): (128*264*2 + 64*264*2 + 64*32*2) bf16 = 210944 B
#define FUSED_SMEM ((128 * 264 * 2 + 64 * 264 * 2 + 64 * 32 * 2) * 2)

extern "C" void kernel_launch(void* const* d_in, const int* in_sizes, int n_in,
                              void* d_out, int out_size)
{
    (void)in_sizes; (void)n_in; (void)out_size;
    const float* x  = (const float*)d_in[0];
    const float* W0 = (const float*)d_in[1];
    const float* U0 = (const float*)d_in[2];
    const float* b0 = (const float*)d_in[3];
    const float* W1 = (const float*)d_in[4];
    const float* U1 = (const float*)d_in[5];
    const float* b1 = (const float*)d_in[6];
    const float* W2 = (const float*)d_in[7];
    const float* U2 = (const float*)d_in[8];
    const float* b2 = (const float*)d_in[9];
    const float* Wd = (const float*)d_in[10];
    const float* bd = (const float*)d_in[11];
    float* out = (float*)d_out;

    void* p;
    cudaGetSymbolAddress(&p, g_xW);    float* xw = (float*)p;
    cudaGetSymbolAddress(&p, g_Ahi);   bf16* ahi = (bf16*)p;
    cudaGetSymbolAddress(&p, g_Alo);   bf16* alo = (bf16*)p;
    cudaGetSymbolAddress(&p, g_Wthi);  bf16* whi = (bf16*)p;
    cudaGetSymbolAddress(&p, g_Wtlo);  bf16* wlo = (bf16*)p;
    cudaGetSymbolAddress(&p, g_Uthi);  bf16* uhi = (bf16*)p;
    cudaGetSymbolAddress(&p, g_Utlo);  bf16* ulo = (bf16*)p;
    cudaGetSymbolAddress(&p, g_bias);  float* bp0 = (float*)p;
    cudaGetSymbolAddress(&p, g_biasP); float* bpP = (float*)p;

    cudaFuncSetAttribute(mma_gemm, cudaFuncAttributeMaxDynamicSharedMemorySize, GEMM_SMEM);
    cudaFuncSetAttribute(fused_lstm, cudaFuncAttributeMaxDynamicSharedMemorySize, FUSED_SMEM);

    // Weight transpose + split + gate-pack (all layers)
    conv_w_packed<<<(1024 * 64  + 255) / 256, 256>>>(W0, whi + WOFF0, wlo + WOFF0, 64,  256);
    conv_w_packed<<<(1024 * 256 + 255) / 256, 256>>>(W1, whi + WOFF1, wlo + WOFF1, 256, 256);
    conv_w_packed<<<(512  * 256 + 255) / 256, 256>>>(W2, whi + WOFF2, wlo + WOFF2, 256, 128);
    conv_w_packed<<<(1024 * 256 + 255) / 256, 256>>>(U0, uhi + UOFF0, ulo + UOFF0, 256, 256);
    conv_w_packed<<<(1024 * 256 + 255) / 256, 256>>>(U1, uhi + UOFF1, ulo + UOFF1, 256, 256);
    conv_w_packed<<<(512  * 128 + 255) / 256, 256>>>(U2, uhi + UOFF2, ulo + UOFF2, 128, 128);

    // Biases (packed order)
    conv_bias<<<4, 256>>>(b0, bp0, 256);
    conv_bias<<<4, 256>>>(b1, bpP, 256);
    conv_bias<<<2, 256>>>(b2, bpP + 1024, 128);

    // Layer-0 xW precompute (x known upfront)
    conv_split<<<(MTOT * 64 / 4 + 255) / 256, 256>>>(x, ahi, alo, MTOT * 64 / 4);
    mma_gemm<<<dim3(8, MTOT / 128), 256, GEMM_SMEM>>>(ahi, alo, whi + WOFF0, wlo + WOFF0,
                                                      bp0, xw, 64, 1024);

    // Pipelined 3-layer wavefront
    reset_sync<<<1, 256>>>();
    fused_lstm<<<128, 256, FUSED_SMEM>>>();

    // Dense head
    dense_kernel<<<BSZ, 64>>>(Wd, bd, out);
}

// round 10
// speedup vs baseline: 3.8002x; 1.0309x over previous
#include <cuda_runtime.h>
#include <cuda_bf16.h>
#include <cstdint>
#include <cstddef>

#define BSZ  256
#define TLEN 512
#define DIN  64
#define MTOT (BSZ * TLEN)

typedef __nv_bfloat16 bf16;

// ---------------------------------------------------------------------------
// Device-global scratch
// ---------------------------------------------------------------------------
__device__ float g_xW[MTOT * 1024];            // xW0 = x@W0 + b0, packed cols
__device__ bf16  g_Ahi[MTOT * 64];             // x split (layer-0 GEMM A)
__device__ bf16  g_Alo[MTOT * 64];
__device__ bf16  g_Wthi[458752];               // W^T packed (3 layers), hi
__device__ bf16  g_Wtlo[458752];
__device__ bf16  g_Uthi[589824];               // U^T packed (3 layers)
__device__ bf16  g_Utlo[589824];
__device__ float g_bias[1024];                 // packed b0 (for xW GEMM)
__device__ float g_biasP[1536];                // packed b1 [0:1024), b2 [1024:1536)
__device__ bf16  g_H0hi[MTOT * 256];           // h sequences (bf16 split)
__device__ bf16  g_H0lo[MTOT * 256];
__device__ bf16  g_H1hi[MTOT * 256];
__device__ bf16  g_H1lo[MTOT * 256];
__device__ bf16  g_H2hi[MTOT * 128];
__device__ bf16  g_H2lo[MTOT * 128];
__device__ unsigned int g_prog[8];             // [0..3]=L0 bb, [4..7]=L1 bb
__device__ unsigned int g_bcnt[12 * 32];       // 12 group-barrier slots, padded
__device__ unsigned int g_bgen[12 * 32];

#define WOFF0 0
#define WOFF1 (1024 * 64)
#define WOFF2 (1024 * 64 + 1024 * 256)
#define UOFF0 0
#define UOFF1 (1024 * 256)
#define UOFF2 (2 * 1024 * 256)

// ---------------------------------------------------------------------------
// sm_100-safe helpers (ldmatrix + mma.sync; no tcgen05)
// ---------------------------------------------------------------------------
__device__ __forceinline__ uint32_t smem_u32(const void* p) {
    uint32_t a;
    asm("{ .reg .u64 t; cvta.to.shared.u64 t, %1; cvt.u32.u64 %0, t; }"
        : "=r"(a) : "l"(p));
    return a;
}
__device__ __forceinline__ void ldsm_x4(uint32_t* r, uint32_t addr) {
    asm volatile("ldmatrix.sync.aligned.m8n8.x4.shared.b16 {%0,%1,%2,%3}, [%4];"
                 : "=r"(r[0]), "=r"(r[1]), "=r"(r[2]), "=r"(r[3]) : "r"(addr));
}
__device__ __forceinline__ void ldsm_x2(uint32_t* r, uint32_t addr) {
    asm volatile("ldmatrix.sync.aligned.m8n8.x2.shared.b16 {%0,%1}, [%2];"
                 : "=r"(r[0]), "=r"(r[1]) : "r"(addr));
}
__device__ __forceinline__ void mma_16816(float* d, const uint32_t* a, const uint32_t* b) {
    asm volatile(
        "mma.sync.aligned.m16n8k16.row.col.f32.bf16.bf16.f32 "
        "{%0,%1,%2,%3}, {%4,%5,%6,%7}, {%8,%9}, {%0,%1,%2,%3};\n"
        : "+f"(d[0]), "+f"(d[1]), "+f"(d[2]), "+f"(d[3])
        : "r"(a[0]), "r"(a[1]), "r"(a[2]), "r"(a[3]), "r"(b[0]), "r"(b[1]));
}
__device__ __forceinline__ float sigf(float x) {
    return __fdividef(1.f, 1.f + __expf(-x));
}
__device__ __forceinline__ float tanhf_(float x) {
    return 1.f - __fdividef(2.f, 1.f + __expf(2.f * x));
}

// ---------------------------------------------------------------------------
// Bounded sync primitives (a bug degrades to wrong output, never a hang)
// ---------------------------------------------------------------------------
__device__ __forceinline__ void wait_prog_ge(int slot, unsigned int tgt) {
    if (threadIdx.x == 0) {
        for (int it = 0; it < (1 << 18); it++) {
            if (*(volatile unsigned int*)&g_prog[slot] >= tgt) break;
            if (it >= 64) __nanosleep(32);
        }
        __threadfence();
    }
    __syncthreads();
}

__device__ __forceinline__ void group_barrier_n(int slot, unsigned int n) {
    __syncthreads();
    if (threadIdx.x == 0) {
        __threadfence();
        unsigned int* cnt = &g_bcnt[slot * 32];
        unsigned int* gen = &g_bgen[slot * 32];
        unsigned int g = atomicAdd(gen, 0u);
        unsigned int arr = atomicAdd(cnt, 1u);
        if (arr == n - 1u) {
            *cnt = 0u;
            __threadfence();
            atomicAdd(gen, 1u);
        } else {
            for (int it = 0; it < (1 << 18); it++) {
                if (*(volatile unsigned int*)gen != g) break;
                if (it >= 128) __nanosleep(32);
            }
        }
        __threadfence();
    }
    __syncthreads();
}

__global__ void reset_sync() {
    int i = threadIdx.x;
    if (i < 8) g_prog[i] = 0;
    for (int j = i; j < 12 * 32; j += 256) { g_bcnt[j] = 0; g_bgen[j] = 0; }
}

// ---------------------------------------------------------------------------
// Conversion kernels (consolidated: 1 launch for all weights, 1 for biases)
// ---------------------------------------------------------------------------
__device__ __forceinline__ void conv_one(const float* __restrict__ M,
                                         bf16* __restrict__ hi, bf16* __restrict__ lo,
                                         int idx, int K, int Hdim)
{
    int N = 4 * Hdim;
    int P = idx / K, k = idx - P * K;
    int n = (P & 3) * Hdim + (P >> 2);
    float v = M[(size_t)k * N + n];
    bf16 h = __float2bfloat16_rn(v);
    hi[idx] = h;
    lo[idx] = __float2bfloat16_rn(v - __bfloat162float(h));
}

__global__ void conv_weights_all(const float* __restrict__ W0, const float* __restrict__ W1,
                                 const float* __restrict__ W2, const float* __restrict__ U0,
                                 const float* __restrict__ U1, const float* __restrict__ U2,
                                 bf16* __restrict__ whi, bf16* __restrict__ wlo,
                                 bf16* __restrict__ uhi, bf16* __restrict__ ulo)
{
    int idx = blockIdx.x * blockDim.x + threadIdx.x;
    if (idx < 65536)        conv_one(W0, whi + WOFF0, wlo + WOFF0, idx, 64, 256);
    else if (idx < 327680)  conv_one(W1, whi + WOFF1, wlo + WOFF1, idx - 65536, 256, 256);
    else if (idx < 458752)  conv_one(W2, whi + WOFF2, wlo + WOFF2, idx - 327680, 256, 128);
    else if (idx < 720896)  conv_one(U0, uhi + UOFF0, ulo + UOFF0, idx - 458752, 256, 256);
    else if (idx < 983040)  conv_one(U1, uhi + UOFF1, ulo + UOFF1, idx - 720896, 256, 256);
    else if (idx < 1048576) conv_one(U2, uhi + UOFF2, ulo + UOFF2, idx - 983040, 128, 128);
}

__global__ void conv_bias_all(const float* __restrict__ b0, const float* __restrict__ b1,
                              const float* __restrict__ b2,
                              float* __restrict__ bp0, float* __restrict__ bpP)
{
    int i = blockIdx.x * blockDim.x + threadIdx.x;
    if (i < 1024)       bp0[i] = b0[(i & 3) * 256 + (i >> 2)];
    else if (i < 2048)  { int P = i - 1024; bpP[P] = b1[(P & 3) * 256 + (P >> 2)]; }
    else if (i < 2560)  { int P = i - 2048; bpP[1024 + P] = b2[(P & 3) * 128 + (P >> 2)]; }
}

__global__ void conv_split(const float* __restrict__ in,
                           bf16* __restrict__ hi, bf16* __restrict__ lo, int n4)
{
    int i = blockIdx.x * blockDim.x + threadIdx.x;
    if (i >= n4) return;
    float4 v = ((const float4*)in)[i];
    union { bf16 b[4]; uint2 u; } H, L;
    H.b[0] = __float2bfloat16_rn(v.x);
    H.b[1] = __float2bfloat16_rn(v.y);
    H.b[2] = __float2bfloat16_rn(v.z);
    H.b[3] = __float2bfloat16_rn(v.w);
    L.b[0] = __float2bfloat16_rn(v.x - __bfloat162float(H.b[0]));
    L.b[1] = __float2bfloat16_rn(v.y - __bfloat162float(H.b[1]));
    L.b[2] = __float2bfloat16_rn(v.z - __bfloat162float(H.b[2]));
    L.b[3] = __float2bfloat16_rn(v.w - __bfloat162float(H.b[3]));
    ((uint2*)hi)[i] = H.u;
    ((uint2*)lo)[i] = L.u;
}

// ---------------------------------------------------------------------------
// mma.sync GEMM (proven): used only for layer-0 xW precompute (K=64)
// ---------------------------------------------------------------------------
#define TSTRIDE 72
#define GEMM_SMEM (4 * 128 * TSTRIDE * 2)

__global__ __launch_bounds__(256)
void mma_gemm(const bf16* __restrict__ Ahi, const bf16* __restrict__ Alo,
              const bf16* __restrict__ Bhi, const bf16* __restrict__ Blo,
              const float* __restrict__ bias, float* __restrict__ C, int K, int N)
{
    extern __shared__ bf16 sm[];
    bf16* sAhi = sm;
    bf16* sAlo = sm + 128 * TSTRIDE;
    bf16* sBhi = sm + 2 * 128 * TSTRIDE;
    bf16* sBlo = sm + 3 * 128 * TSTRIDE;
    const uint32_t uAhi = smem_u32(sAhi), uAlo = smem_u32(sAlo);
    const uint32_t uBhi = smem_u32(sBhi), uBlo = smem_u32(sBlo);

    const int tid = threadIdx.x;
    const int wid = tid >> 5, lane = tid & 31;
    const int warp_m = wid & 1, warp_n = wid >> 1;
    const int bm = blockIdx.y * 128, bn = blockIdx.x * 128;

    float acc[4][4][4];
#pragma unroll
    for (int mi = 0; mi < 4; mi++)
#pragma unroll
        for (int ni = 0; ni < 4; ni++)
#pragma unroll
            for (int f = 0; f < 4; f++) acc[mi][ni][f] = 0.f;

    const int r8  = lane & 7;
    const int grp = lane >> 3;
    const int aRowOff = ((grp & 1) ? 8 : 0) + r8;
    const int aColOff = (grp & 2) ? 8 : 0;
    const int bSel = grp & 1;

    const int nchunk = K >> 6;
    for (int c = 0; c < nchunk; c++) {
        const int k0g = c << 6;
#pragma unroll
        for (int i = 0; i < 4; i++) {
            int idx = tid + i * 256;
            int row = idx >> 3, seg = idx & 7;
            size_t ga = (size_t)(bm + row) * K + k0g + seg * 8;
            size_t gb = (size_t)(bn + row) * K + k0g + seg * 8;
            int so = row * TSTRIDE + seg * 8;
            *(uint4*)(sAhi + so) = *(const uint4*)&Ahi[ga];
            *(uint4*)(sAlo + so) = *(const uint4*)&Alo[ga];
            *(uint4*)(sBhi + so) = *(const uint4*)&Bhi[gb];
            *(uint4*)(sBlo + so) = *(const uint4*)&Blo[gb];
        }
        __syncthreads();

#pragma unroll
        for (int ks = 0; ks < 4; ks++) {
            const int k0 = ks * 16;
            uint32_t aHi[4][4], aLo[4][4], bHi[4][2], bLo[4][2];
#pragma unroll
            for (int mi = 0; mi < 4; mi++) {
                int row = warp_m * 64 + mi * 16 + aRowOff;
                uint32_t off = (uint32_t)(row * TSTRIDE + k0 + aColOff) * 2;
                ldsm_x4(aHi[mi], uAhi + off);
                ldsm_x4(aLo[mi], uAlo + off);
            }
#pragma unroll
            for (int ni = 0; ni < 4; ni++) {
                int row = warp_n * 32 + ni * 8 + r8;
                uint32_t off = (uint32_t)(row * TSTRIDE + k0 + bSel * 8) * 2;
                ldsm_x2(bHi[ni], uBhi + off);
                ldsm_x2(bLo[ni], uBlo + off);
            }
#pragma unroll
            for (int mi = 0; mi < 4; mi++)
#pragma unroll
                for (int ni = 0; ni < 4; ni++) {
                    mma_16816(acc[mi][ni], aHi[mi], bHi[ni]);
                    mma_16816(acc[mi][ni], aHi[mi], bLo[ni]);
                    mma_16816(acc[mi][ni], aLo[mi], bHi[ni]);
                }
        }
        __syncthreads();
    }

    const int tg = lane >> 2, tp = lane & 3;
#pragma unroll
    for (int mi = 0; mi < 4; mi++) {
#pragma unroll
        for (int ni = 0; ni < 4; ni++) {
            int col = bn + warp_n * 32 + ni * 8 + tp * 2;
            int row0 = bm + warp_m * 64 + mi * 16 + tg;
            float2 o0, o1;
            o0.x = acc[mi][ni][0] + bias[col];
            o0.y = acc[mi][ni][1] + bias[col + 1];
            o1.x = acc[mi][ni][2] + bias[col];
            o1.y = acc[mi][ni][3] + bias[col + 1];
            *(float2*)&C[(size_t)row0 * N + col] = o0;
            *(float2*)&C[(size_t)(row0 + 8) * N + col] = o1;
        }
    }
}

// ---------------------------------------------------------------------------
// Fused wavefront LSTM: 3 layers pipelined over t in one persistent kernel.
// Phase order (KIN>0): U-GEMM (own h(t-1), ready at round start) FIRST, then
// cross-layer wait + input W-GEMM -> wavefront skew hides under U compute.
// Step-invariant U-hi ldsm fragments hoisted to registers when NI<=2.
// ---------------------------------------------------------------------------
template<int HDIM, int KIN, int UPCv, int GRPN>
__device__ void run_layer(int bb, int cb, int gslot, int pubslot, int waitslot,
    const bf16* __restrict__ Uthi, const bf16* __restrict__ Utlo,
    const bf16* __restrict__ Wthi, const bf16* __restrict__ Wtlo,
    const float* __restrict__ biasp, const float* __restrict__ xW,
    const bf16* __restrict__ Hin_hi, const bf16* __restrict__ Hin_lo,
    bf16* __restrict__ Hhi, bf16* __restrict__ Hlo)
{
    constexpr int K    = HDIM;
    constexpr int PC   = 4 * UPCv;
    constexpr int WN   = PC / 4;
    constexpr int NI   = WN / 8;
    constexpr int KSU  = K / 16;
    constexpr int KS2U = K + 8;
    constexpr int U4U  = K / 8;
    constexpr int KSW  = KIN / 16;
    constexpr int KS2W = KIN + 8;
    constexpr int U4W  = KIN / 8;
    constexpr int KS2M = (KS2W > KS2U) ? KS2W : KS2U;
    constexpr int STW  = UPCv / 2;
    constexpr bool HOIST = (NI <= 2);

    extern __shared__ bf16 dyn[];
    bf16* sUhi  = dyn;                               // PC x KS2U
    bf16* sUlo  = sUhi + PC * KS2U;
    bf16* sWhi  = sUlo + PC * KS2U;                  // PC x KS2W (if KIN)
    bf16* sWlo  = sWhi + (KIN ? PC * KS2W : 0);
    bf16* sHs_hi = sWlo + (KIN ? PC * KS2W : 0);     // 64 x KS2M (A staging)
    bf16* sHs_lo = sHs_hi + 64 * KS2M;
    bf16* sSthi  = sHs_lo + 64 * KS2M;               // 64 x UPC stage-out
    bf16* sStlo  = sSthi + 64 * UPCv;
    const uint32_t uUhi = smem_u32(sUhi), uUlo = smem_u32(sUlo);
    const uint32_t uWhi = smem_u32(sWhi), uWlo = smem_u32(sWlo);
    const uint32_t uHhi = smem_u32(sHs_hi), uHlo = smem_u32(sHs_lo);

    const int tid = threadIdx.x;
    const int wid = tid >> 5, lane = tid & 31;
    const int wm = wid & 1, wn = wid >> 1;
    const int b0 = bb * 64;

    const int r8  = lane & 7;
    const int grp = lane >> 3;
    const int aRowOff = ((grp & 1) ? 8 : 0) + r8;
    const int aColOff = (grp & 2) ? 8 : 0;
    const int bSel = grp & 1;
    const int tg = lane >> 2, tp = lane & 3;
    const bool evenp = (tp & 1) == 0;

    // Persistent U^T slice (packed rows cb*PC ..)
    for (int idx = tid; idx < PC * U4U; idx += 256) {
        int p = idx / U4U, q = idx - p * U4U;
        size_t g = (size_t)(cb * PC + p) * K + q * 8;
        *(uint4*)(sUhi + p * KS2U + q * 8) = *(const uint4*)&Uthi[g];
        *(uint4*)(sUlo + p * KS2U + q * 8) = *(const uint4*)&Utlo[g];
    }
    if constexpr (KIN > 0) {
        for (int idx = tid; idx < PC * U4W; idx += 256) {
            int p = idx / U4W, q = idx - p * U4W;
            size_t g = (size_t)(cb * PC + p) * KIN + q * 8;
            *(uint4*)(sWhi + p * KS2W + q * 8) = *(const uint4*)&Wthi[g];
            *(uint4*)(sWlo + p * KS2W + q * 8) = *(const uint4*)&Wtlo[g];
        }
    }
    __syncthreads();

    // Hoist step-invariant U-hi fragments into registers (small NI only)
    uint32_t uHiReg[HOIST ? KSU : 1][HOIST ? NI : 1][2];
    if constexpr (HOIST) {
#pragma unroll
        for (int ks = 0; ks < KSU; ks++)
#pragma unroll
            for (int ni = 0; ni < NI; ni++) {
                uint32_t off = (uint32_t)((wn * WN + ni * 8 + r8) * KS2U
                                          + ks * 16 + bSel * 8) * 2;
                ldsm_x2(uHiReg[ks][ni], uUhi + off);
            }
    }

    int colg[NI], uLoc[NI];
#pragma unroll
    for (int ni = 0; ni < NI; ni++) {
        int pcl = wn * WN + ni * 8 + 2 * tp;
        colg[ni] = cb * PC + pcl;
        uLoc[ni] = pcl >> 2;
    }
    float bs[NI][2];
    if constexpr (KIN > 0) {
#pragma unroll
        for (int ni = 0; ni < NI; ni++) {
            bs[ni][0] = biasp[colg[ni]];
            bs[ni][1] = biasp[colg[ni] + 1];
        }
    }

    float cst[2][NI][2];
#pragma unroll
    for (int mi = 0; mi < 2; mi++)
#pragma unroll
        for (int ni = 0; ni < NI; ni++) { cst[mi][ni][0] = 0.f; cst[mi][ni][1] = 0.f; }

    float nxt[2][NI][4];
    if constexpr (KIN == 0) {
#pragma unroll
        for (int mi = 0; mi < 2; mi++) {
            size_t row = (size_t)(b0 + wm * 32 + mi * 16 + tg);
#pragma unroll
            for (int ni = 0; ni < NI; ni++) {
                float2 a = *(const float2*)&xW[(row * TLEN) * (4 * HDIM) + colg[ni]];
                float2 b = *(const float2*)&xW[((row + 8) * TLEN) * (4 * HDIM) + colg[ni]];
                nxt[mi][ni][0] = a.x; nxt[mi][ni][1] = a.y;
                nxt[mi][ni][2] = b.x; nxt[mi][ni][3] = b.y;
            }
        }
    }

    for (int t = 0; t < TLEN; t++) {
        float acc[2][NI][4];
#pragma unroll
        for (int mi = 0; mi < 2; mi++)
#pragma unroll
            for (int ni = 0; ni < NI; ni++) {
                if constexpr (KIN == 0) {
                    acc[mi][ni][0] = nxt[mi][ni][0]; acc[mi][ni][1] = nxt[mi][ni][1];
                    acc[mi][ni][2] = nxt[mi][ni][2]; acc[mi][ni][3] = nxt[mi][ni][3];
                } else {
                    acc[mi][ni][0] = bs[ni][0]; acc[mi][ni][1] = bs[ni][1];
                    acc[mi][ni][2] = bs[ni][0]; acc[mi][ni][3] = bs[ni][1];
                }
            }

        // ---- Recurrent GEMM FIRST (own h(t-1) is ready at round start) ----
        if (t > 0) {
            for (int idx = tid; idx < 64 * U4U; idx += 256) {
                int r = idx / U4U, q = idx - r * U4U;
                size_t g = ((size_t)(b0 + r) * TLEN + (t - 1)) * HDIM + q * 8;
                *(uint4*)(sHs_hi + r * KS2U + q * 8) = *(const uint4*)&Hhi[g];
                *(uint4*)(sHs_lo + r * KS2U + q * 8) = *(const uint4*)&Hlo[g];
            }
            __syncthreads();
#pragma unroll
            for (int ks = 0; ks < KSU; ks++) {
                uint32_t ahi[2][4], alo[2][4];
#pragma unroll
                for (int mi = 0; mi < 2; mi++) {
                    uint32_t aoff = (uint32_t)((wm * 32 + mi * 16 + aRowOff) * KS2U
                                               + ks * 16 + aColOff) * 2;
                    ldsm_x4(ahi[mi], uHhi + aoff);
                    ldsm_x4(alo[mi], uHlo + aoff);
                }
#pragma unroll
                for (int ni = 0; ni < NI; ni++) {
                    uint32_t bh[2], bl[2];
                    uint32_t boff = (uint32_t)((wn * WN + ni * 8 + r8) * KS2U
                                               + ks * 16 + bSel * 8) * 2;
                    if constexpr (HOIST) {
                        bh[0] = uHiReg[ks][ni][0]; bh[1] = uHiReg[ks][ni][1];
                    } else {
                        ldsm_x2(bh, uUhi + boff);
                    }
                    ldsm_x2(bl, uUlo + boff);
#pragma unroll
                    for (int mi = 0; mi < 2; mi++) {
                        mma_16816(acc[mi][ni], ahi[mi], bh);
                        mma_16816(acc[mi][ni], ahi[mi], bl);
                        mma_16816(acc[mi][ni], alo[mi], bh);
                    }
                }
            }
            __syncthreads();   // sHs reads done before W-phase restages
        }

        // ---- Cross-layer wait + input GEMM (skew hidden under U-phase) ----
        if constexpr (KIN > 0) {
            wait_prog_ge(waitslot, (unsigned)(t + 1));
            for (int idx = tid; idx < 64 * U4W; idx += 256) {
                int r = idx / U4W, q = idx - r * U4W;
                size_t g = ((size_t)(b0 + r) * TLEN + t) * KIN + q * 8;
                *(uint4*)(sHs_hi + r * KS2W + q * 8) = *(const uint4*)&Hin_hi[g];
                *(uint4*)(sHs_lo + r * KS2W + q * 8) = *(const uint4*)&Hin_lo[g];
            }
            __syncthreads();
#pragma unroll
            for (int ks = 0; ks < KSW; ks++) {
                uint32_t ahi[2][4], alo[2][4];
#pragma unroll
                for (int mi = 0; mi < 2; mi++) {
                    uint32_t aoff = (uint32_t)((wm * 32 + mi * 16 + aRowOff) * KS2W
                                               + ks * 16 + aColOff) * 2;
                    ldsm_x4(ahi[mi], uHhi + aoff);
                    ldsm_x4(alo[mi], uHlo + aoff);
                }
#pragma unroll
                for (int ni = 0; ni < NI; ni++) {
                    uint32_t bh[2], bl[2];
                    uint32_t boff = (uint32_t)((wn * WN + ni * 8 + r8) * KS2W
                                               + ks * 16 + bSel * 8) * 2;
                    ldsm_x2(bh, uWhi + boff);
                    ldsm_x2(bl, uWlo + boff);
#pragma unroll
                    for (int mi = 0; mi < 2; mi++) {
                        mma_16816(acc[mi][ni], ahi[mi], bh);
                        mma_16816(acc[mi][ni], ahi[mi], bl);
                        mma_16816(acc[mi][ni], alo[mi], bh);
                    }
                }
            }
        }

        // Gates (even tp: i,f | odd tp: g,o of same unit); stage h out
#pragma unroll
        for (int mi = 0; mi < 2; mi++) {
#pragma unroll
            for (int ni = 0; ni < NI; ni++) {
                float v0, v1, v2, v3;
                if (evenp) {
                    v0 = sigf(acc[mi][ni][0]); v1 = sigf(acc[mi][ni][1]);
                    v2 = sigf(acc[mi][ni][2]); v3 = sigf(acc[mi][ni][3]);
                } else {
                    v0 = tanhf_(acc[mi][ni][0]); v1 = sigf(acc[mi][ni][1]);
                    v2 = tanhf_(acc[mi][ni][2]); v3 = sigf(acc[mi][ni][3]);
                }
                float p0 = __shfl_xor_sync(0xffffffffu, v0, 1);
                float p1 = __shfl_xor_sync(0xffffffffu, v1, 1);
                float p2 = __shfl_xor_sync(0xffffffffu, v2, 1);
                float p3 = __shfl_xor_sync(0xffffffffu, v3, 1);
                float i0 = evenp ? v0 : p0, f0 = evenp ? v1 : p1;
                float g0 = evenp ? p0 : v0, o0 = evenp ? p1 : v1;
                float i1 = evenp ? v2 : p2, f1 = evenp ? v3 : p3;
                float g1 = evenp ? p2 : v2, o1 = evenp ? p3 : v3;

                float c0 = fmaf(f0, cst[mi][ni][0], i0 * g0);
                float c1 = fmaf(f1, cst[mi][ni][1], i1 * g1);
                cst[mi][ni][0] = c0;
                cst[mi][ni][1] = c1;
                float h0 = o0 * tanhf_(c0);
                float h1 = o1 * tanhf_(c1);

                if (evenp) {
                    int r0 = wm * 32 + mi * 16 + tg, r1 = r0 + 8;
                    bf16 h0h = __float2bfloat16_rn(h0);
                    bf16 h1h = __float2bfloat16_rn(h1);
                    sSthi[r0 * UPCv + uLoc[ni]] = h0h;
                    sStlo[r0 * UPCv + uLoc[ni]] = __float2bfloat16_rn(h0 - __bfloat162float(h0h));
                    sSthi[r1 * UPCv + uLoc[ni]] = h1h;
                    sStlo[r1 * UPCv + uLoc[ni]] = __float2bfloat16_rn(h1 - __bfloat162float(h1h));
                }
            }
        }

        // L0: prefetch next xW (hidden under store + barrier)
        if constexpr (KIN == 0) {
            if (t + 1 < TLEN) {
#pragma unroll
                for (int mi = 0; mi < 2; mi++) {
                    size_t row = (size_t)(b0 + wm * 32 + mi * 16 + tg);
#pragma unroll
                    for (int ni = 0; ni < NI; ni++) {
                        float2 a = *(const float2*)&xW[(row * TLEN + t + 1) * (4 * HDIM) + colg[ni]];
                        float2 b = *(const float2*)&xW[((row + 8) * TLEN + t + 1) * (4 * HDIM) + colg[ni]];
                        nxt[mi][ni][0] = a.x; nxt[mi][ni][1] = a.y;
                        nxt[mi][ni][2] = b.x; nxt[mi][ni][3] = b.y;
                    }
                }
            }
        }

        __syncthreads();
        // Coalesced h store (hi & lo)
        for (int idx = tid; idx < 64 * STW; idx += 256) {
            int r = idx / STW, q = idx - r * STW;
            size_t g = ((size_t)(b0 + r) * TLEN + t) * HDIM + cb * UPCv + q * 2;
            *(uint32_t*)&Hhi[g] = ((const uint32_t*)sSthi)[r * STW + q];
            *(uint32_t*)&Hlo[g] = ((const uint32_t*)sStlo)[r * STW + q];
        }

        group_barrier_n(gslot, GRPN);
        if (pubslot >= 0 && cb == 0 && tid == 0)
            atomicExch(&g_prog[pubslot], (unsigned)(t + 1));
    }
}

__global__ __launch_bounds__(256, 1) void fused_lstm()
{
    int bx = blockIdx.x;
    if (bx < 32) {
        int bb = bx >> 3, cb = bx & 7;
        run_layer<256, 0, 32, 8>(bb, cb, bb, bb, -1,
            g_Uthi + UOFF0, g_Utlo + UOFF0, nullptr, nullptr,
            nullptr, g_xW, nullptr, nullptr, g_H0hi, g_H0lo);
    } else if (bx < 96) {
        int l = bx - 32;
        int bb = l >> 4, cb = l & 15;
        run_layer<256, 256, 16, 16>(bb, cb, 4 + bb, 4 + bb, bb,
            g_Uthi + UOFF1, g_Utlo + UOFF1, g_Wthi + WOFF1, g_Wtlo + WOFF1,
            g_biasP, nullptr, g_H0hi, g_H0lo, g_H1hi, g_H1lo);
    } else {
        int l = bx - 96;
        int bb = l >> 3, cb = l & 7;
        run_layer<128, 256, 16, 8>(bb, cb, 8 + bb, -1, 4 + bb,
            g_Uthi + UOFF2, g_Utlo + UOFF2, g_Wthi + WOFF2, g_Wtlo + WOFF2,
            g_biasP + 1024, nullptr, g_H1hi, g_H1lo, g_H2hi, g_H2lo);
    }
}

// ---------------------------------------------------------------------------
// Final dense: out[b,d] = (hi+lo)[b,T-1,:128] @ Wd + bd
// ---------------------------------------------------------------------------
__global__ void dense_kernel(const float* __restrict__ Wd, const float* __restrict__ bd,
                             float* __restrict__ out)
{
    int b = blockIdx.x;
    int d = threadIdx.x;
    size_t base = ((size_t)b * TLEN + (TLEN - 1)) * 128;
    float acc = 0.f;
#pragma unroll 4
    for (int k = 0; k < 128; k++) {
        float h = __bfloat162float(g_H2hi[base + k]) + __bfloat162float(g_H2lo[base + k]);
        acc = fmaf(h, Wd[k * 64 + d], acc);
    }
    out[b * 64 + d] = acc + bd[d];
}

// ---------------------------------------------------------------------------
// Launch sequence (fused_lstm is launch #5 -> ncu -s 5 -c 1 captures it)
// ---------------------------------------------------------------------------
#define FUSED_SMEM ((128 * 264 * 2 + 64 * 264 * 2 + 64 * 32 * 2) * 2)

extern "C" void kernel_launch(void* const* d_in, const int* in_sizes, int n_in,
                              void* d_out, int out_size)
{
    (void)in_sizes; (void)n_in; (void)out_size;
    const float* x  = (const float*)d_in[0];
    const float* W0 = (const float*)d_in[1];
    const float* U0 = (const float*)d_in[2];
    const float* b0 = (const float*)d_in[3];
    const float* W1 = (const float*)d_in[4];
    const float* U1 = (const float*)d_in[5];
    const float* b1 = (const float*)d_in[6];
    const float* W2 = (const float*)d_in[7];
    const float* U2 = (const float*)d_in[8];
    const float* b2 = (const float*)d_in[9];
    const float* Wd = (const float*)d_in[10];
    const float* bd = (const float*)d_in[11];
    float* out = (float*)d_out;

    void* p;
    cudaGetSymbolAddress(&p, g_xW);    float* xw = (float*)p;
    cudaGetSymbolAddress(&p, g_Ahi);   bf16* ahi = (bf16*)p;
    cudaGetSymbolAddress(&p, g_Alo);   bf16* alo = (bf16*)p;
    cudaGetSymbolAddress(&p, g_Wthi);  bf16* whi = (bf16*)p;
    cudaGetSymbolAddress(&p, g_Wtlo);  bf16* wlo = (bf16*)p;
    cudaGetSymbolAddress(&p, g_Uthi);  bf16* uhi = (bf16*)p;
    cudaGetSymbolAddress(&p, g_Utlo);  bf16* ulo = (bf16*)p;
    cudaGetSymbolAddress(&p, g_bias);  float* bp0 = (float*)p;
    cudaGetSymbolAddress(&p, g_biasP); float* bpP = (float*)p;

    cudaFuncSetAttribute(mma_gemm, cudaFuncAttributeMaxDynamicSharedMemorySize, GEMM_SMEM);
    cudaFuncSetAttribute(fused_lstm, cudaFuncAttributeMaxDynamicSharedMemorySize, FUSED_SMEM);

    // [0] all weight transposes/splits, one launch
    conv_weights_all<<<4096, 256>>>(W0, W1, W2, U0, U1, U2, whi, wlo, uhi, ulo);
    // [1] all biases
    conv_bias_all<<<10, 256>>>(b0, b1, b2, bp0, bpP);
    // [2] x split
    conv_split<<<(MTOT * 64 / 4 + 255) / 256, 256>>>(x, ahi, alo, MTOT * 64 / 4);
    // [3] layer-0 xW precompute
    mma_gemm<<<dim3(8, MTOT / 128), 256, GEMM_SMEM>>>(ahi, alo, whi + WOFF0, wlo + WOFF0,
                                                      bp0, xw, 64, 1024);
    // [4] sync reset, [5] fused wavefront (ncu target), [6] dense head
    reset_sync<<<1, 256>>>();
    fused_lstm<<<128, 256, FUSED_SMEM>>>();
    dense_kernel<<<BSZ, 64>>>(Wd, bd, out);
}

// round 12
// speedup vs baseline: 3.8774x; 1.0203x over previous
#include <cuda_runtime.h>
#include <cuda_bf16.h>
#include <cstdint>
#include <cstddef>

#define BSZ  256
#define TLEN 512
#define DIN  64
#define MTOT (BSZ * TLEN)

typedef __nv_bfloat16 bf16;

// ---------------------------------------------------------------------------
// Device-global scratch
// ---------------------------------------------------------------------------
__device__ float g_xW[MTOT * 1024];            // xW0 = x@W0 + b0, packed cols
__device__ bf16  g_Ahi[MTOT * 64];             // x split (layer-0 GEMM A)
__device__ bf16  g_Alo[MTOT * 64];
__device__ bf16  g_Wthi[458752];               // W^T packed (3 layers), hi
__device__ bf16  g_Wtlo[458752];
__device__ bf16  g_Uthi[589824];               // U^T packed (3 layers)
__device__ bf16  g_Utlo[589824];
__device__ float g_bias[1024];                 // packed b0 (for xW GEMM)
__device__ float g_biasP[1536];                // packed b1 [0:1024), b2 [1024:1536)
__device__ bf16  g_H0hi[MTOT * 256];           // h sequences (bf16 split)
__device__ bf16  g_H0lo[MTOT * 256];
__device__ bf16  g_H1hi[MTOT * 256];
__device__ bf16  g_H1lo[MTOT * 256];
__device__ bf16  g_H2hi[MTOT * 128];
__device__ bf16  g_H2lo[MTOT * 128];
__device__ unsigned int g_prog[8];             // [0..3]=L0 bb, [4..7]=L1 bb
__device__ unsigned int g_bcnt[12 * 32];       // 12 group-barrier slots, padded
__device__ unsigned int g_bgen[12 * 32];

#define WOFF0 0
#define WOFF1 (1024 * 64)
#define WOFF2 (1024 * 64 + 1024 * 256)
#define UOFF0 0
#define UOFF1 (1024 * 256)
#define UOFF2 (2 * 1024 * 256)

// ---------------------------------------------------------------------------
// sm_100-safe helpers (ldmatrix + mma.sync; no tcgen05)
// ---------------------------------------------------------------------------
__device__ __forceinline__ uint32_t smem_u32(const void* p) {
    uint32_t a;
    asm("{ .reg .u64 t; cvta.to.shared.u64 t, %1; cvt.u32.u64 %0, t; }"
        : "=r"(a) : "l"(p));
    return a;
}
__device__ __forceinline__ void ldsm_x4(uint32_t* r, uint32_t addr) {
    asm volatile("ldmatrix.sync.aligned.m8n8.x4.shared.b16 {%0,%1,%2,%3}, [%4];"
                 : "=r"(r[0]), "=r"(r[1]), "=r"(r[2]), "=r"(r[3]) : "r"(addr));
}
__device__ __forceinline__ void ldsm_x2(uint32_t* r, uint32_t addr) {
    asm volatile("ldmatrix.sync.aligned.m8n8.x2.shared.b16 {%0,%1}, [%2];"
                 : "=r"(r[0]), "=r"(r[1]) : "r"(addr));
}
__device__ __forceinline__ void mma_16816(float* d, const uint32_t* a, const uint32_t* b) {
    asm volatile(
        "mma.sync.aligned.m16n8k16.row.col.f32.bf16.bf16.f32 "
        "{%0,%1,%2,%3}, {%4,%5,%6,%7}, {%8,%9}, {%0,%1,%2,%3};\n"
        : "+f"(d[0]), "+f"(d[1]), "+f"(d[2]), "+f"(d[3])
        : "r"(a[0]), "r"(a[1]), "r"(a[2]), "r"(a[3]), "r"(b[0]), "r"(b[1]));
}
__device__ __forceinline__ float sigf(float x) {
    return __fdividef(1.f, 1.f + __expf(-x));
}
__device__ __forceinline__ float tanhf_(float x) {
    return 1.f - __fdividef(2.f, 1.f + __expf(2.f * x));
}

// ---------------------------------------------------------------------------
// Bounded sync primitives. Raw spin first (poll rate is limited by L2 latency,
// 1 thread/CTA so traffic is trivial); nanosleep only as a late fallback to
// avoid its coarse quantization on the common path. A bug degrades to wrong
// output, never a container-killing hang.
// ---------------------------------------------------------------------------
__device__ __forceinline__ void wait_prog_ge(int slot, unsigned int tgt) {
    if (threadIdx.x == 0) {
        bool ok = false;
        for (int it = 0; it < 4096; it++) {
            if (*(volatile unsigned int*)&g_prog[slot] >= tgt) { ok = true; break; }
        }
        if (!ok) {
            for (int it = 0; it < (1 << 18); it++) {
                if (*(volatile unsigned int*)&g_prog[slot] >= tgt) break;
                __nanosleep(64);
            }
        }
        __threadfence();
    }
    __syncthreads();
}

__device__ __forceinline__ void group_barrier_n(int slot, unsigned int n) {
    __syncthreads();
    if (threadIdx.x == 0) {
        __threadfence();
        unsigned int* cnt = &g_bcnt[slot * 32];
        unsigned int* gen = &g_bgen[slot * 32];
        unsigned int g = atomicAdd(gen, 0u);
        unsigned int arr = atomicAdd(cnt, 1u);
        if (arr == n - 1u) {
            *cnt = 0u;
            __threadfence();
            atomicAdd(gen, 1u);
        } else {
            bool ok = false;
            for (int it = 0; it < 4096; it++) {
                if (*(volatile unsigned int*)gen != g) { ok = true; break; }
            }
            if (!ok) {
                for (int it = 0; it < (1 << 18); it++) {
                    if (*(volatile unsigned int*)gen != g) break;
                    __nanosleep(64);
                }
            }
        }
        __threadfence();
    }
    __syncthreads();
}

// ---------------------------------------------------------------------------
// Consolidated conversion kernel: weight transposes/splits + bias permute +
// sync reset, all in ONE launch (keeps fused_lstm at launch index 3).
// ---------------------------------------------------------------------------
__device__ __forceinline__ void conv_one(const float* __restrict__ M,
                                         bf16* __restrict__ hi, bf16* __restrict__ lo,
                                         int idx, int K, int Hdim)
{
    int N = 4 * Hdim;
    int P = idx / K, k = idx - P * K;
    int n = (P & 3) * Hdim + (P >> 2);
    float v = M[(size_t)k * N + n];
    bf16 h = __float2bfloat16_rn(v);
    hi[idx] = h;
    lo[idx] = __float2bfloat16_rn(v - __bfloat162float(h));
}

__global__ void conv_all(const float* __restrict__ W0, const float* __restrict__ W1,
                         const float* __restrict__ W2, const float* __restrict__ U0,
                         const float* __restrict__ U1, const float* __restrict__ U2,
                         const float* __restrict__ b0, const float* __restrict__ b1,
                         const float* __restrict__ b2,
                         bf16* __restrict__ whi, bf16* __restrict__ wlo,
                         bf16* __restrict__ uhi, bf16* __restrict__ ulo,
                         float* __restrict__ bp0, float* __restrict__ bpP)
{
    int idx = blockIdx.x * blockDim.x + threadIdx.x;
    if (idx < 65536)        conv_one(W0, whi + WOFF0, wlo + WOFF0, idx, 64, 256);
    else if (idx < 327680)  conv_one(W1, whi + WOFF1, wlo + WOFF1, idx - 65536, 256, 256);
    else if (idx < 458752)  conv_one(W2, whi + WOFF2, wlo + WOFF2, idx - 327680, 256, 128);
    else if (idx < 720896)  conv_one(U0, uhi + UOFF0, ulo + UOFF0, idx - 458752, 256, 256);
    else if (idx < 983040)  conv_one(U1, uhi + UOFF1, ulo + UOFF1, idx - 720896, 256, 256);
    else if (idx < 1048576) conv_one(U2, uhi + UOFF2, ulo + UOFF2, idx - 983040, 128, 128);
    else {
        int i = idx - 1048576;
        if (i < 1024)       bp0[i] = b0[(i & 3) * 256 + (i >> 2)];
        else if (i < 2048)  { int P = i - 1024; bpP[P] = b1[(P & 3) * 256 + (P >> 2)]; }
        else if (i < 2560)  { int P = i - 2048; bpP[1024 + P] = b2[(P & 3) * 128 + (P >> 2)]; }
        else if (i < 2568)  g_prog[i - 2560] = 0;
        else if (i < 2952)  { int j = i - 2568; g_bcnt[j] = 0; g_bgen[j] = 0; }
    }
}

__global__ void conv_split(const float* __restrict__ in,
                           bf16* __restrict__ hi, bf16* __restrict__ lo, int n4)
{
    int i = blockIdx.x * blockDim.x + threadIdx.x;
    if (i >= n4) return;
    float4 v = ((const float4*)in)[i];
    union { bf16 b[4]; uint2 u; } H, L;
    H.b[0] = __float2bfloat16_rn(v.x);
    H.b[1] = __float2bfloat16_rn(v.y);
    H.b[2] = __float2bfloat16_rn(v.z);
    H.b[3] = __float2bfloat16_rn(v.w);
    L.b[0] = __float2bfloat16_rn(v.x - __bfloat162float(H.b[0]));
    L.b[1] = __float2bfloat16_rn(v.y - __bfloat162float(H.b[1]));
    L.b[2] = __float2bfloat16_rn(v.z - __bfloat162float(H.b[2]));
    L.b[3] = __float2bfloat16_rn(v.w - __bfloat162float(H.b[3]));
    ((uint2*)hi)[i] = H.u;
    ((uint2*)lo)[i] = L.u;
}

// ---------------------------------------------------------------------------
// mma.sync GEMM (proven): used only for layer-0 xW precompute (K=64)
// ---------------------------------------------------------------------------
#define TSTRIDE 72
#define GEMM_SMEM (4 * 128 * TSTRIDE * 2)

__global__ __launch_bounds__(256)
void mma_gemm(const bf16* __restrict__ Ahi, const bf16* __restrict__ Alo,
              const bf16* __restrict__ Bhi, const bf16* __restrict__ Blo,
              const float* __restrict__ bias, float* __restrict__ C, int K, int N)
{
    extern __shared__ bf16 sm[];
    bf16* sAhi = sm;
    bf16* sAlo = sm + 128 * TSTRIDE;
    bf16* sBhi = sm + 2 * 128 * TSTRIDE;
    bf16* sBlo = sm + 3 * 128 * TSTRIDE;
    const uint32_t uAhi = smem_u32(sAhi), uAlo = smem_u32(sAlo);
    const uint32_t uBhi = smem_u32(sBhi), uBlo = smem_u32(sBlo);

    const int tid = threadIdx.x;
    const int wid = tid >> 5, lane = tid & 31;
    const int warp_m = wid & 1, warp_n = wid >> 1;
    const int bm = blockIdx.y * 128, bn = blockIdx.x * 128;

    float acc[4][4][4];
#pragma unroll
    for (int mi = 0; mi < 4; mi++)
#pragma unroll
        for (int ni = 0; ni < 4; ni++)
#pragma unroll
            for (int f = 0; f < 4; f++) acc[mi][ni][f] = 0.f;

    const int r8  = lane & 7;
    const int grp = lane >> 3;
    const int aRowOff = ((grp & 1) ? 8 : 0) + r8;
    const int aColOff = (grp & 2) ? 8 : 0;
    const int bSel = grp & 1;

    const int nchunk = K >> 6;
    for (int c = 0; c < nchunk; c++) {
        const int k0g = c << 6;
#pragma unroll
        for (int i = 0; i < 4; i++) {
            int idx = tid + i * 256;
            int row = idx >> 3, seg = idx & 7;
            size_t ga = (size_t)(bm + row) * K + k0g + seg * 8;
            size_t gb = (size_t)(bn + row) * K + k0g + seg * 8;
            int so = row * TSTRIDE + seg * 8;
            *(uint4*)(sAhi + so) = *(const uint4*)&Ahi[ga];
            *(uint4*)(sAlo + so) = *(const uint4*)&Alo[ga];
            *(uint4*)(sBhi + so) = *(const uint4*)&Bhi[gb];
            *(uint4*)(sBlo + so) = *(const uint4*)&Blo[gb];
        }
        __syncthreads();

#pragma unroll
        for (int ks = 0; ks < 4; ks++) {
            const int k0 = ks * 16;
            uint32_t aHi[4][4], aLo[4][4], bHi[4][2], bLo[4][2];
#pragma unroll
            for (int mi = 0; mi < 4; mi++) {
                int row = warp_m * 64 + mi * 16 + aRowOff;
                uint32_t off = (uint32_t)(row * TSTRIDE + k0 + aColOff) * 2;
                ldsm_x4(aHi[mi], uAhi + off);
                ldsm_x4(aLo[mi], uAlo + off);
            }
#pragma unroll
            for (int ni = 0; ni < 4; ni++) {
                int row = warp_n * 32 + ni * 8 + r8;
                uint32_t off = (uint32_t)(row * TSTRIDE + k0 + bSel * 8) * 2;
                ldsm_x2(bHi[ni], uBhi + off);
                ldsm_x2(bLo[ni], uBlo + off);
            }
#pragma unroll
            for (int mi = 0; mi < 4; mi++)
#pragma unroll
                for (int ni = 0; ni < 4; ni++) {
                    mma_16816(acc[mi][ni], aHi[mi], bHi[ni]);
                    mma_16816(acc[mi][ni], aHi[mi], bLo[ni]);
                    mma_16816(acc[mi][ni], aLo[mi], bHi[ni]);
                }
        }
        __syncthreads();
    }

    const int tg = lane >> 2, tp = lane & 3;
#pragma unroll
    for (int mi = 0; mi < 4; mi++) {
#pragma unroll
        for (int ni = 0; ni < 4; ni++) {
            int col = bn + warp_n * 32 + ni * 8 + tp * 2;
            int row0 = bm + warp_m * 64 + mi * 16 + tg;
            float2 o0, o1;
            o0.x = acc[mi][ni][0] + bias[col];
            o0.y = acc[mi][ni][1] + bias[col + 1];
            o1.x = acc[mi][ni][2] + bias[col];
            o1.y = acc[mi][ni][3] + bias[col + 1];
            *(float2*)&C[(size_t)row0 * N + col] = o0;
            *(float2*)&C[(size_t)(row0 + 8) * N + col] = o1;
        }
    }
}

// ---------------------------------------------------------------------------
// Fused wavefront LSTM: 3 layers pipelined over t in one persistent kernel.
// U-GEMM first (own h(t-1) ready at round start), then cross-layer wait +
// input W-GEMM. U-hi fragments hoisted to registers when NI<=2.
// ---------------------------------------------------------------------------
template<int HDIM, int KIN, int UPCv, int GRPN>
__device__ void run_layer(int bb, int cb, int gslot, int pubslot, int waitslot,
    const bf16* __restrict__ Uthi, const bf16* __restrict__ Utlo,
    const bf16* __restrict__ Wthi, const bf16* __restrict__ Wtlo,
    const float* __restrict__ biasp, const float* __restrict__ xW,
    const bf16* __restrict__ Hin_hi, const bf16* __restrict__ Hin_lo,
    bf16* __restrict__ Hhi, bf16* __restrict__ Hlo)
{
    constexpr int K    = HDIM;
    constexpr int PC   = 4 * UPCv;
    constexpr int WN   = PC / 4;
    constexpr int NI   = WN / 8;
    constexpr int KSU  = K / 16;
    constexpr int KS2U = K + 8;
    constexpr int U4U  = K / 8;
    constexpr int KSW  = KIN / 16;
    constexpr int KS2W = KIN + 8;
    constexpr int U4W  = KIN / 8;
    constexpr int KS2M = (KS2W > KS2U) ? KS2W : KS2U;
    constexpr int STW  = UPCv / 2;
    constexpr bool HOIST = (NI <= 2);

    extern __shared__ bf16 dyn[];
    bf16* sUhi  = dyn;                               // PC x KS2U
    bf16* sUlo  = sUhi + PC * KS2U;
    bf16* sWhi  = sUlo + PC * KS2U;                  // PC x KS2W (if KIN)
    bf16* sWlo  = sWhi + (KIN ? PC * KS2W : 0);
    bf16* sHs_hi = sWlo + (KIN ? PC * KS2W : 0);     // 64 x KS2M (A staging)
    bf16* sHs_lo = sHs_hi + 64 * KS2M;
    bf16* sSthi  = sHs_lo + 64 * KS2M;               // 64 x UPC stage-out
    bf16* sStlo  = sSthi + 64 * UPCv;
    const uint32_t uUhi = smem_u32(sUhi), uUlo = smem_u32(sUlo);
    const uint32_t uWhi = smem_u32(sWhi), uWlo = smem_u32(sWlo);
    const uint32_t uHhi = smem_u32(sHs_hi), uHlo = smem_u32(sHs_lo);

    const int tid = threadIdx.x;
    const int wid = tid >> 5, lane = tid & 31;
    const int wm = wid & 1, wn = wid >> 1;
    const int b0 = bb * 64;

    const int r8  = lane & 7;
    const int grp = lane >> 3;
    const int aRowOff = ((grp & 1) ? 8 : 0) + r8;
    const int aColOff = (grp & 2) ? 8 : 0;
    const int bSel = grp & 1;
    const int tg = lane >> 2, tp = lane & 3;
    const bool evenp = (tp & 1) == 0;

    // Persistent U^T slice (packed rows cb*PC ..)
    for (int idx = tid; idx < PC * U4U; idx += 256) {
        int p = idx / U4U, q = idx - p * U4U;
        size_t g = (size_t)(cb * PC + p) * K + q * 8;
        *(uint4*)(sUhi + p * KS2U + q * 8) = *(const uint4*)&Uthi[g];
        *(uint4*)(sUlo + p * KS2U + q * 8) = *(const uint4*)&Utlo[g];
    }
    if constexpr (KIN > 0) {
        for (int idx = tid; idx < PC * U4W; idx += 256) {
            int p = idx / U4W, q = idx - p * U4W;
            size_t g = (size_t)(cb * PC + p) * KIN + q * 8;
            *(uint4*)(sWhi + p * KS2W + q * 8) = *(const uint4*)&Wthi[g];
            *(uint4*)(sWlo + p * KS2W + q * 8) = *(const uint4*)&Wtlo[g];
        }
    }
    __syncthreads();

    // Hoist step-invariant U-hi fragments into registers (small NI only)
    uint32_t uHiReg[HOIST ? KSU : 1][HOIST ? NI : 1][2];
    if constexpr (HOIST) {
#pragma unroll
        for (int ks = 0; ks < KSU; ks++)
#pragma unroll
            for (int ni = 0; ni < NI; ni++) {
                uint32_t off = (uint32_t)((wn * WN + ni * 8 + r8) * KS2U
                                          + ks * 16 + bSel * 8) * 2;
                ldsm_x2(uHiReg[ks][ni], uUhi + off);
            }
    }

    int colg[NI], uLoc[NI];
#pragma unroll
    for (int ni = 0; ni < NI; ni++) {
        int pcl = wn * WN + ni * 8 + 2 * tp;
        colg[ni] = cb * PC + pcl;
        uLoc[ni] = pcl >> 2;
    }
    float bs[NI][2];
    if constexpr (KIN > 0) {
#pragma unroll
        for (int ni = 0; ni < NI; ni++) {
            bs[ni][0] = biasp[colg[ni]];
            bs[ni][1] = biasp[colg[ni] + 1];
        }
    }

    float cst[2][NI][2];
#pragma unroll
    for (int mi = 0; mi < 2; mi++)
#pragma unroll
        for (int ni = 0; ni < NI; ni++) { cst[mi][ni][0] = 0.f; cst[mi][ni][1] = 0.f; }

    float nxt[2][NI][4];
    if constexpr (KIN == 0) {
#pragma unroll
        for (int mi = 0; mi < 2; mi++) {
            size_t row = (size_t)(b0 + wm * 32 + mi * 16 + tg);
#pragma unroll
            for (int ni = 0; ni < NI; ni++) {
                float2 a = *(const float2*)&xW[(row * TLEN) * (4 * HDIM) + colg[ni]];
                float2 b = *(const float2*)&xW[((row + 8) * TLEN) * (4 * HDIM) + colg[ni]];
                nxt[mi][ni][0] = a.x; nxt[mi][ni][1] = a.y;
                nxt[mi][ni][2] = b.x; nxt[mi][ni][3] = b.y;
            }
        }
    }

    for (int t = 0; t < TLEN; t++) {
        float acc[2][NI][4];
#pragma unroll
        for (int mi = 0; mi < 2; mi++)
#pragma unroll
            for (int ni = 0; ni < NI; ni++) {
                if constexpr (KIN == 0) {
                    acc[mi][ni][0] = nxt[mi][ni][0]; acc[mi][ni][1] = nxt[mi][ni][1];
                    acc[mi][ni][2] = nxt[mi][ni][2]; acc[mi][ni][3] = nxt[mi][ni][3];
                } else {
                    acc[mi][ni][0] = bs[ni][0]; acc[mi][ni][1] = bs[ni][1];
                    acc[mi][ni][2] = bs[ni][0]; acc[mi][ni][3] = bs[ni][1];
                }
            }

        // ---- Recurrent GEMM FIRST (own h(t-1) is ready at round start) ----
        if (t > 0) {
            for (int idx = tid; idx < 64 * U4U; idx += 256) {
                int r = idx / U4U, q = idx - r * U4U;
                size_t g = ((size_t)(b0 + r) * TLEN + (t - 1)) * HDIM + q * 8;
                *(uint4*)(sHs_hi + r * KS2U + q * 8) = *(const uint4*)&Hhi[g];
                *(uint4*)(sHs_lo + r * KS2U + q * 8) = *(const uint4*)&Hlo[g];
            }
            __syncthreads();
#pragma unroll
            for (int ks = 0; ks < KSU; ks++) {
                uint32_t ahi[2][4], alo[2][4];
#pragma unroll
                for (int mi = 0; mi < 2; mi++) {
                    uint32_t aoff = (uint32_t)((wm * 32 + mi * 16 + aRowOff) * KS2U
                                               + ks * 16 + aColOff) * 2;
                    ldsm_x4(ahi[mi], uHhi + aoff);
                    ldsm_x4(alo[mi], uHlo + aoff);
                }
#pragma unroll
                for (int ni = 0; ni < NI; ni++) {
                    uint32_t bh[2], bl[2];
                    uint32_t boff = (uint32_t)((wn * WN + ni * 8 + r8) * KS2U
                                               + ks * 16 + bSel * 8) * 2;
                    if constexpr (HOIST) {
                        bh[0] = uHiReg[ks][ni][0]; bh[1] = uHiReg[ks][ni][1];
                    } else {
                        ldsm_x2(bh, uUhi + boff);
                    }
                    ldsm_x2(bl, uUlo + boff);
#pragma unroll
                    for (int mi = 0; mi < 2; mi++) {
                        mma_16816(acc[mi][ni], ahi[mi], bh);
                        mma_16816(acc[mi][ni], ahi[mi], bl);
                        mma_16816(acc[mi][ni], alo[mi], bh);
                    }
                }
            }
            __syncthreads();   // sHs reads done before W-phase restages
        }

        // ---- Cross-layer wait + input GEMM (skew hidden under U-phase) ----
        if constexpr (KIN > 0) {
            wait_prog_ge(waitslot, (unsigned)(t + 1));
            for (int idx = tid; idx < 64 * U4W; idx += 256) {
                int r = idx / U4W, q = idx - r * U4W;
                size_t g = ((size_t)(b0 + r) * TLEN + t) * KIN + q * 8;
                *(uint4*)(sHs_hi + r * KS2W + q * 8) = *(const uint4*)&Hin_hi[g];
                *(uint4*)(sHs_lo + r * KS2W + q * 8) = *(const uint4*)&Hin_lo[g];
            }
            __syncthreads();
#pragma unroll
            for (int ks = 0; ks < KSW; ks++) {
                uint32_t ahi[2][4], alo[2][4];
#pragma unroll
                for (int mi = 0; mi < 2; mi++) {
                    uint32_t aoff = (uint32_t)((wm * 32 + mi * 16 + aRowOff) * KS2W
                                               + ks * 16 + aColOff) * 2;
                    ldsm_x4(ahi[mi], uHhi + aoff);
                    ldsm_x4(alo[mi], uHlo + aoff);
                }
#pragma unroll
                for (int ni = 0; ni < NI; ni++) {
                    uint32_t bh[2], bl[2];
                    uint32_t boff = (uint32_t)((wn * WN + ni * 8 + r8) * KS2W
                                               + ks * 16 + bSel * 8) * 2;
                    ldsm_x2(bh, uWhi + boff);
                    ldsm_x2(bl, uWlo + boff);
#pragma unroll
                    for (int mi = 0; mi < 2; mi++) {
                        mma_16816(acc[mi][ni], ahi[mi], bh);
                        mma_16816(acc[mi][ni], ahi[mi], bl);
                        mma_16816(acc[mi][ni], alo[mi], bh);
                    }
                }
            }
        }

        // Gates (even tp: i,f | odd tp: g,o of same unit); stage h out
#pragma unroll
        for (int mi = 0; mi < 2; mi++) {
#pragma unroll
            for (int ni = 0; ni < NI; ni++) {
                float v0, v1, v2, v3;
                if (evenp) {
                    v0 = sigf(acc[mi][ni][0]); v1 = sigf(acc[mi][ni][1]);
                    v2 = sigf(acc[mi][ni][2]); v3 = sigf(acc[mi][ni][3]);
                } else {
                    v0 = tanhf_(acc[mi][ni][0]); v1 = sigf(acc[mi][ni][1]);
                    v2 = tanhf_(acc[mi][ni][2]); v3 = sigf(acc[mi][ni][3]);
                }
                float p0 = __shfl_xor_sync(0xffffffffu, v0, 1);
                float p1 = __shfl_xor_sync(0xffffffffu, v1, 1);
                float p2 = __shfl_xor_sync(0xffffffffu, v2, 1);
                float p3 = __shfl_xor_sync(0xffffffffu, v3, 1);
                float i0 = evenp ? v0 : p0, f0 = evenp ? v1 : p1;
                float g0 = evenp ? p0 : v0, o0 = evenp ? p1 : v1;
                float i1 = evenp ? v2 : p2, f1 = evenp ? v3 : p3;
                float g1 = evenp ? p2 : v2, o1 = evenp ? p3 : v3;

                float c0 = fmaf(f0, cst[mi][ni][0], i0 * g0);
                float c1 = fmaf(f1, cst[mi][ni][1], i1 * g1);
                cst[mi][ni][0] = c0;
                cst[mi][ni][1] = c1;
                float h0 = o0 * tanhf_(c0);
                float h1 = o1 * tanhf_(c1);

                if (evenp) {
                    int r0 = wm * 32 + mi * 16 + tg, r1 = r0 + 8;
                    bf16 h0h = __float2bfloat16_rn(h0);
                    bf16 h1h = __float2bfloat16_rn(h1);
                    sSthi[r0 * UPCv + uLoc[ni]] = h0h;
                    sStlo[r0 * UPCv + uLoc[ni]] = __float2bfloat16_rn(h0 - __bfloat162float(h0h));
                    sSthi[r1 * UPCv + uLoc[ni]] = h1h;
                    sStlo[r1 * UPCv + uLoc[ni]] = __float2bfloat16_rn(h1 - __bfloat162float(h1h));
                }
            }
        }

        // L0: prefetch next xW (hidden under store + barrier)
        if constexpr (KIN == 0) {
            if (t + 1 < TLEN) {
#pragma unroll
                for (int mi = 0; mi < 2; mi++) {
                    size_t row = (size_t)(b0 + wm * 32 + mi * 16 + tg);
#pragma unroll
                    for (int ni = 0; ni < NI; ni++) {
                        float2 a = *(const float2*)&xW[(row * TLEN + t + 1) * (4 * HDIM) + colg[ni]];
                        float2 b = *(const float2*)&xW[((row + 8) * TLEN + t + 1) * (4 * HDIM) + colg[ni]];
                        nxt[mi][ni][0] = a.x; nxt[mi][ni][1] = a.y;
                        nxt[mi][ni][2] = b.x; nxt[mi][ni][3] = b.y;
                    }
                }
            }
        }

        __syncthreads();
        // Coalesced h store (hi & lo)
        for (int idx = tid; idx < 64 * STW; idx += 256) {
            int r = idx / STW, q = idx - r * STW;
            size_t g = ((size_t)(b0 + r) * TLEN + t) * HDIM + cb * UPCv + q * 2;
            *(uint32_t*)&Hhi[g] = ((const uint32_t*)sSthi)[r * STW + q];
            *(uint32_t*)&Hlo[g] = ((const uint32_t*)sStlo)[r * STW + q];
        }

        group_barrier_n(gslot, GRPN);
        if (pubslot >= 0 && cb == 0 && tid == 0)
            atomicExch(&g_prog[pubslot], (unsigned)(t + 1));
    }
}

__global__ __launch_bounds__(256, 1) void fused_lstm()
{
    int bx = blockIdx.x;
    if (bx < 32) {
        int bb = bx >> 3, cb = bx & 7;
        run_layer<256, 0, 32, 8>(bb, cb, bb, bb, -1,
            g_Uthi + UOFF0, g_Utlo + UOFF0, nullptr, nullptr,
            nullptr, g_xW, nullptr, nullptr, g_H0hi, g_H0lo);
    } else if (bx < 96) {
        int l = bx - 32;
        int bb = l >> 4, cb = l & 15;
        run_layer<256, 256, 16, 16>(bb, cb, 4 + bb, 4 + bb, bb,
            g_Uthi + UOFF1, g_Utlo + UOFF1, g_Wthi + WOFF1, g_Wtlo + WOFF1,
            g_biasP, nullptr, g_H0hi, g_H0lo, g_H1hi, g_H1lo);
    } else {
        int l = bx - 96;
        int bb = l >> 3, cb = l & 7;
        run_layer<128, 256, 16, 8>(bb, cb, 8 + bb, -1, 4 + bb,
            g_Uthi + UOFF2, g_Utlo + UOFF2, g_Wthi + WOFF2, g_Wtlo + WOFF2,
            g_biasP + 1024, nullptr, g_H1hi, g_H1lo, g_H2hi, g_H2lo);
    }
}

// ---------------------------------------------------------------------------
// Final dense: out[b,d] = (hi+lo)[b,T-1,:128] @ Wd + bd
// ---------------------------------------------------------------------------
__global__ void dense_kernel(const float* __restrict__ Wd, const float* __restrict__ bd,
                             float* __restrict__ out)
{
    int b = blockIdx.x;
    int d = threadIdx.x;
    size_t base = ((size_t)b * TLEN + (TLEN - 1)) * 128;
    float acc = 0.f;
#pragma unroll 4
    for (int k = 0; k < 128; k++) {
        float h = __bfloat162float(g_H2hi[base + k]) + __bfloat162float(g_H2lo[base + k]);
        acc = fmaf(h, Wd[k * 64 + d], acc);
    }
    out[b * 64 + d] = acc + bd[d];
}

// ---------------------------------------------------------------------------
// Launch sequence: [0] conv_all  [1] conv_split  [2] mma_gemm
//                  [3] fused_lstm (ncu -s5 target w/ +2 harness offset)
//                  [4] dense
// ---------------------------------------------------------------------------
#define FUSED_SMEM ((128 * 264 * 2 + 64 * 264 * 2 + 64 * 32 * 2) * 2)

extern "C" void kernel_launch(void* const* d_in, const int* in_sizes, int n_in,
                              void* d_out, int out_size)
{
    (void)in_sizes; (void)n_in; (void)out_size;
    const float* x  = (const float*)d_in[0];
    const float* W0 = (const float*)d_in[1];
    const float* U0 = (const float*)d_in[2];
    const float* b0 = (const float*)d_in[3];
    const float* W1 = (const float*)d_in[4];
    const float* U1 = (const float*)d_in[5];
    const float* b1 = (const float*)d_in[6];
    const float* W2 = (const float*)d_in[7];
    const float* U2 = (const float*)d_in[8];
    const float* b2 = (const float*)d_in[9];
    const float* Wd = (const float*)d_in[10];
    const float* bd = (const float*)d_in[11];
    float* out = (float*)d_out;

    void* p;
    cudaGetSymbolAddress(&p, g_xW);    float* xw = (float*)p;
    cudaGetSymbolAddress(&p, g_Ahi);   bf16* ahi = (bf16*)p;
    cudaGetSymbolAddress(&p, g_Alo);   bf16* alo = (bf16*)p;
    cudaGetSymbolAddress(&p, g_Wthi);  bf16* whi = (bf16*)p;
    cudaGetSymbolAddress(&p, g_Wtlo);  bf16* wlo = (bf16*)p;
    cudaGetSymbolAddress(&p, g_Uthi);  bf16* uhi = (bf16*)p;
    cudaGetSymbolAddress(&p, g_Utlo);  bf16* ulo = (bf16*)p;
    cudaGetSymbolAddress(&p, g_bias);  float* bp0 = (float*)p;
    cudaGetSymbolAddress(&p, g_biasP); float* bpP = (float*)p;

    cudaFuncSetAttribute(mma_gemm, cudaFuncAttributeMaxDynamicSharedMemorySize, GEMM_SMEM);
    cudaFuncSetAttribute(fused_lstm, cudaFuncAttributeMaxDynamicSharedMemorySize, FUSED_SMEM);

    // [0] all weight/bias conversion + sync reset (one launch)
    conv_all<<<4108, 256>>>(W0, W1, W2, U0, U1, U2, b0, b1, b2,
                            whi, wlo, uhi, ulo, bp0, bpP);
    // [1] x split
    conv_split<<<(MTOT * 64 / 4 + 255) / 256, 256>>>(x, ahi, alo, MTOT * 64 / 4);
    // [2] layer-0 xW precompute
    mma_gemm<<<dim3(8, MTOT / 128), 256, GEMM_SMEM>>>(ahi, alo, whi + WOFF0, wlo + WOFF0,
                                                      bp0, xw, 64, 1024);
    // [3] fused wavefront (profiling target)
    fused_lstm<<<128, 256, FUSED_SMEM>>>();
    // [4] dense head
    dense_kernel<<<BSZ, 64>>>(Wd, bd, out);
}